// round 1
// baseline (speedup 1.0000x reference)
#include <cuda_runtime.h>
#include <cuda_bf16.h>
#include <cstdint>

// ---------------- problem constants ----------------
#define BB 4
#define NN 8192
#define CC 512
#define HH 4
#define DD 128
#define HID 2048
#define MTOK (BB*NN)          // 32768
#define EPS 1e-5f
#define SCALE 0.08838834764831845f   // 128^-0.5

// ---------------- scratch (static device globals; no allocs allowed) ----
__device__ float g_xn  [(size_t)MTOK * CC];          // 64 MB (LN1 out, reused as LN2 out)
__device__ float g_qkv [(size_t)MTOK * 3 * CC];      // 192 MB
__device__ float g_attn[(size_t)MTOK * CC];          // 64 MB
__device__ float g_x1  [(size_t)MTOK * CC];          // 64 MB
__device__ float g_mlph[(size_t)MTOK * HID];         // 256 MB
__device__ float g_ctxp[(size_t)32 * 16 * DD * DD];  // 32 MB (split-K partials)
__device__ float g_ctx [(size_t)16 * DD * DD];       // 1 MB

// ---------------- LayerNorm over 512 (one block per row) ----------------
__global__ void ln_rows512(const float* __restrict__ x, float* __restrict__ y,
                           const float* __restrict__ w, const float* __restrict__ b) {
    int row = blockIdx.x;
    const float* xr = x + (size_t)row * CC;
    int t = threadIdx.x;                     // 256 threads
    float v0 = xr[t], v1 = xr[t + 256];
    float s = v0 + v1, s2 = v0 * v0 + v1 * v1;
#pragma unroll
    for (int o = 16; o > 0; o >>= 1) {
        s  += __shfl_xor_sync(0xffffffffu, s,  o);
        s2 += __shfl_xor_sync(0xffffffffu, s2, o);
    }
    __shared__ float sh[18];
    int wid = t >> 5, lane = t & 31;
    if (lane == 0) { sh[wid] = s; sh[wid + 8] = s2; }
    __syncthreads();
    if (t == 0) {
        float ts = 0.f, ts2 = 0.f;
#pragma unroll
        for (int i = 0; i < 8; i++) { ts += sh[i]; ts2 += sh[i + 8]; }
        float mu  = ts * (1.f / CC);
        float var = ts2 * (1.f / CC) - mu * mu;
        sh[16] = mu; sh[17] = rsqrtf(var + EPS);
    }
    __syncthreads();
    float mu = sh[16], inv = sh[17];
    float* yr = y + (size_t)row * CC;
    yr[t]       = (v0 - mu) * inv * w[t]       + b[t];
    yr[t + 256] = (v1 - mu) * inv * w[t + 256] + b[t + 256];
}

// ---------------- LayerNorm over 128 for k,v slices (warp per row, in place) ----
__global__ void ln_kv(float* __restrict__ qkv,
                      const float* __restrict__ lnk_w, const float* __restrict__ lnk_b,
                      const float* __restrict__ lnv_w, const float* __restrict__ lnv_b) {
    int gwarp = (blockIdx.x * blockDim.x + threadIdx.x) >> 5;   // 0 .. 2*MTOK*HH-1
    int lane  = threadIdx.x & 31;
    int bn   = gwarp >> 3;           // token index (b*N+n)
    int rem  = gwarp & 7;
    int tsel = rem >> 2;             // 0 = k, 1 = v
    int h    = rem & 3;
    size_t base = (size_t)bn * (3 * CC) + (size_t)(1 + tsel) * CC + (size_t)h * DD;
    float4 v = *(const float4*)(qkv + base + lane * 4);
    float s  = v.x + v.y + v.z + v.w;
    float s2 = v.x * v.x + v.y * v.y + v.z * v.z + v.w * v.w;
#pragma unroll
    for (int o = 16; o > 0; o >>= 1) {
        s  += __shfl_xor_sync(0xffffffffu, s,  o);
        s2 += __shfl_xor_sync(0xffffffffu, s2, o);
    }
    float mu  = s * (1.f / DD);
    float var = s2 * (1.f / DD) - mu * mu;
    float inv = rsqrtf(var + EPS);
    const float* w  = tsel ? lnv_w : lnk_w;
    const float* bb = tsel ? lnv_b : lnk_b;
    float4 wv = *(const float4*)(w  + lane * 4);
    float4 bv = *(const float4*)(bb + lane * 4);
    float4 o;
    o.x = (v.x - mu) * inv * wv.x + bv.x;
    o.y = (v.y - mu) * inv * wv.y + bv.y;
    o.z = (v.z - mu) * inv * wv.z + bv.z;
    o.w = (v.w - mu) * inv * wv.w + bv.w;
    *(float4*)(qkv + base + lane * 4) = o;
}

// ---------------- SGEMM: C[M,N] = A[M,K] @ B[K,N] + epilogue ----------------
// BM=BN=128, BK=8, 256 threads, 8x8 microtile, double-buffered smem.
#define EPI_BIAS 0
#define EPI_GELU 1
#define EPI_RES  2

template <int EPI>
__global__ __launch_bounds__(256, 2)
void sgemm_k(const float* __restrict__ A, const float* __restrict__ B,
             float* __restrict__ C, int M, int N, int K,
             const float* __restrict__ bias, const float* __restrict__ res) {
    __shared__ float As[2][8][132];  // transposed A tile, padded
    __shared__ float Bs[2][8][128];
    int tid = threadIdx.x;
    int tx = tid & 15, ty = tid >> 4;
    int m0 = blockIdx.y * 128, n0 = blockIdx.x * 128;

    int arow = tid >> 1;             // 0..127
    int acol = (tid & 1) * 4;        // 0 or 4
    int brow = tid >> 5;             // 0..7
    int bcol = (tid & 31) * 4;       // 0..124

    const float* Aptr = A + (size_t)(m0 + arow) * K + acol;
    const float* Bptr = B + (size_t)brow * N + n0 + bcol;

    float4 a4 = *(const float4*)Aptr;
    float4 b4 = *(const float4*)Bptr;
    As[0][acol + 0][arow] = a4.x; As[0][acol + 1][arow] = a4.y;
    As[0][acol + 2][arow] = a4.z; As[0][acol + 3][arow] = a4.w;
    *(float4*)&Bs[0][brow][bcol] = b4;
    __syncthreads();

    float acc[8][8];
#pragma unroll
    for (int i = 0; i < 8; i++)
#pragma unroll
        for (int j = 0; j < 8; j++) acc[i][j] = 0.f;

    int ntiles = K >> 3;
    int buf = 0;
    for (int t = 0; t < ntiles; ++t) {
        if (t + 1 < ntiles) {
            a4 = *(const float4*)(Aptr + (t + 1) * 8);
            b4 = *(const float4*)(Bptr + (size_t)(t + 1) * 8 * N);
        }
#pragma unroll
        for (int k = 0; k < 8; k++) {
            const float4* ap = (const float4*)&As[buf][k][ty * 8];
            const float4* bp = (const float4*)&Bs[buf][k][tx * 8];
            float4 a0 = ap[0], a1 = ap[1];
            float4 b0 = bp[0], b1 = bp[1];
            float a[8] = {a0.x, a0.y, a0.z, a0.w, a1.x, a1.y, a1.z, a1.w};
            float b[8] = {b0.x, b0.y, b0.z, b0.w, b1.x, b1.y, b1.z, b1.w};
#pragma unroll
            for (int i = 0; i < 8; i++)
#pragma unroll
                for (int j = 0; j < 8; j++) acc[i][j] += a[i] * b[j];
        }
        if (t + 1 < ntiles) {
            buf ^= 1;
            As[buf][acol + 0][arow] = a4.x; As[buf][acol + 1][arow] = a4.y;
            As[buf][acol + 2][arow] = a4.z; As[buf][acol + 3][arow] = a4.w;
            *(float4*)&Bs[buf][brow][bcol] = b4;
            __syncthreads();
        }
    }

#pragma unroll
    for (int i = 0; i < 8; i++) {
        size_t off = (size_t)(m0 + ty * 8 + i) * N + n0 + tx * 8;
#pragma unroll
        for (int j = 0; j < 8; j++) {
            float v = acc[i][j] + bias[n0 + tx * 8 + j];
            if (EPI == EPI_GELU) v = v * normcdff(v);
            if (EPI == EPI_RES)  v += res[off + j];
            C[off + j] = v;
        }
    }
}

// ---------------- context partials: ctxp[split][bh][d][e] = sum_n k[n,d]*v[n,e] ----
__global__ __launch_bounds__(256)
void ctx_partial(const float* __restrict__ qkv, float* __restrict__ ctxp) {
    int bh = blockIdx.x;     // 0..15
    int split = blockIdx.y;  // 0..31
    int b = bh >> 2, h = bh & 3;
    __shared__ float Ks[8][128];
    __shared__ float Vs[8][128];
    int tid = threadIdx.x;
    int tx = tid & 15, ty = tid >> 4;
    int lr = tid >> 5;             // 0..7
    int lc = (tid & 31) * 4;       // 0..124
    float acc[8][8];
#pragma unroll
    for (int i = 0; i < 8; i++)
#pragma unroll
        for (int j = 0; j < 8; j++) acc[i][j] = 0.f;

    int n0 = split * 256;
    for (int t = 0; t < 32; t++) {
        int n = n0 + t * 8 + lr;
        size_t base = ((size_t)b * NN + n) * (3 * CC) + CC + (size_t)h * DD;
        float4 kv = *(const float4*)(qkv + base + lc);
        float4 vv = *(const float4*)(qkv + base + CC + lc);
        __syncthreads();
        *(float4*)&Ks[lr][lc] = kv;
        *(float4*)&Vs[lr][lc] = vv;
        __syncthreads();
#pragma unroll
        for (int k = 0; k < 8; k++) {
            const float4* ap = (const float4*)&Ks[k][ty * 8];
            const float4* bp = (const float4*)&Vs[k][tx * 8];
            float4 a0 = ap[0], a1 = ap[1];
            float4 b0 = bp[0], b1 = bp[1];
            float a[8] = {a0.x, a0.y, a0.z, a0.w, a1.x, a1.y, a1.z, a1.w};
            float bb[8] = {b0.x, b0.y, b0.z, b0.w, b1.x, b1.y, b1.z, b1.w};
#pragma unroll
            for (int i = 0; i < 8; i++)
#pragma unroll
                for (int j = 0; j < 8; j++) acc[i][j] += a[i] * bb[j];
        }
    }
    float* outp = ctxp + ((size_t)split * 16 + bh) * (DD * DD);
#pragma unroll
    for (int i = 0; i < 8; i++)
#pragma unroll
        for (int j = 0; j < 8; j++)
            outp[(size_t)(ty * 8 + i) * DD + tx * 8 + j] = acc[i][j];
}

__global__ void reduce_ctx(const float* __restrict__ ctxp, float* __restrict__ ctx) {
    int i = blockIdx.x * blockDim.x + threadIdx.x;   // 0..262143
    float s = 0.f;
#pragma unroll
    for (int sp = 0; sp < 32; sp++) s += ctxp[(size_t)sp * (16 * DD * DD) + i];
    ctx[i] = s;
}

// ---------------- attn = (q @ ctx) * SCALE, scattered into [M, C] layout -----
__global__ __launch_bounds__(256, 2)
void attn_k(const float* __restrict__ qkv, const float* __restrict__ ctx,
            float* __restrict__ attnb) {
    int mt = blockIdx.x;    // 0..63   n-tile within batch
    int bh = blockIdx.y;    // 0..15
    int b = bh >> 2, h = bh & 3;
    __shared__ float As[8][132];
    __shared__ float Bs[8][128];
    int tid = threadIdx.x;
    int tx = tid & 15, ty = tid >> 4;
    int arow = tid >> 1;           // 0..127 (n-local)
    int acol = (tid & 1) * 4;
    int brow = tid >> 5;
    int bcol = (tid & 31) * 4;

    size_t qbase = ((size_t)b * NN + mt * 128 + arow) * (3 * CC) + (size_t)h * DD;
    const float* cb = ctx + (size_t)bh * (DD * DD);

    float acc[8][8];
#pragma unroll
    for (int i = 0; i < 8; i++)
#pragma unroll
        for (int j = 0; j < 8; j++) acc[i][j] = 0.f;

    for (int t = 0; t < 16; t++) {     // K = 128 = 16 * 8
        float4 a4 = *(const float4*)(qkv + qbase + t * 8 + acol);
        float4 b4 = *(const float4*)(cb + (size_t)(t * 8 + brow) * DD + bcol);
        __syncthreads();
        As[acol + 0][arow] = a4.x; As[acol + 1][arow] = a4.y;
        As[acol + 2][arow] = a4.z; As[acol + 3][arow] = a4.w;
        *(float4*)&Bs[brow][bcol] = b4;
        __syncthreads();
#pragma unroll
        for (int k = 0; k < 8; k++) {
            const float4* ap = (const float4*)&As[k][ty * 8];
            const float4* bp = (const float4*)&Bs[k][tx * 8];
            float4 a0 = ap[0], a1 = ap[1];
            float4 b0 = bp[0], b1 = bp[1];
            float a[8] = {a0.x, a0.y, a0.z, a0.w, a1.x, a1.y, a1.z, a1.w};
            float bb[8] = {b0.x, b0.y, b0.z, b0.w, b1.x, b1.y, b1.z, b1.w};
#pragma unroll
            for (int i = 0; i < 8; i++)
#pragma unroll
                for (int j = 0; j < 8; j++) acc[i][j] += a[i] * bb[j];
        }
    }
#pragma unroll
    for (int i = 0; i < 8; i++) {
        size_t row = (size_t)b * NN + mt * 128 + ty * 8 + i;
        size_t off = row * CC + h * DD + tx * 8;
#pragma unroll
        for (int j = 0; j < 8; j++)
            attnb[off + j] = acc[i][j] * SCALE;
    }
}

// ---------------- launch ----------------
extern "C" void kernel_launch(void* const* d_in, const int* in_sizes, int n_in,
                              void* d_out, int out_size) {
    const float* x       = (const float*)d_in[0];
    const float* norm1_w = (const float*)d_in[1];
    const float* norm1_b = (const float*)d_in[2];
    const float* qkv_w   = (const float*)d_in[3];
    const float* qkv_b   = (const float*)d_in[4];
    const float* lnk_w   = (const float*)d_in[5];
    const float* lnk_b   = (const float*)d_in[6];
    const float* lnv_w   = (const float*)d_in[7];
    const float* lnv_b   = (const float*)d_in[8];
    const float* proj_w  = (const float*)d_in[9];
    const float* proj_b  = (const float*)d_in[10];
    const float* norm2_w = (const float*)d_in[11];
    const float* norm2_b = (const float*)d_in[12];
    const float* mlp_w1  = (const float*)d_in[13];
    const float* mlp_b1  = (const float*)d_in[14];
    const float* mlp_w2  = (const float*)d_in[15];
    const float* mlp_b2  = (const float*)d_in[16];
    float* out = (float*)d_out;

    float *xn, *qkv, *attnb, *x1, *mlph, *ctxp, *ctx;
    cudaGetSymbolAddress((void**)&xn,    g_xn);
    cudaGetSymbolAddress((void**)&qkv,   g_qkv);
    cudaGetSymbolAddress((void**)&attnb, g_attn);
    cudaGetSymbolAddress((void**)&x1,    g_x1);
    cudaGetSymbolAddress((void**)&mlph,  g_mlph);
    cudaGetSymbolAddress((void**)&ctxp,  g_ctxp);
    cudaGetSymbolAddress((void**)&ctx,   g_ctx);

    // 1. LN1
    ln_rows512<<<MTOK, 256>>>(x, xn, norm1_w, norm1_b);
    // 2. qkv = xn @ qkv_w + b
    sgemm_k<EPI_BIAS><<<dim3(12, 256), 256>>>(xn, qkv_w, qkv, MTOK, 3 * CC, CC, qkv_b, nullptr);
    // 3. LN on k and v slices (in place)
    ln_kv<<<32768, 256>>>(qkv, lnk_w, lnk_b, lnv_w, lnv_b);
    // 4. context = k^T v (split-K partials + reduce)
    ctx_partial<<<dim3(16, 32), 256>>>(qkv, ctxp);
    reduce_ctx<<<1024, 256>>>(ctxp, ctx);
    // 5. attn = q @ ctx * scale
    attn_k<<<dim3(64, 16), 256>>>(qkv, ctx, attnb);
    // 6. x1 = x + attn @ proj_w + b
    sgemm_k<EPI_RES><<<dim3(4, 256), 256>>>(attnb, proj_w, x1, MTOK, CC, CC, proj_b, x);
    // 7. LN2
    ln_rows512<<<MTOK, 256>>>(x1, xn, norm2_w, norm2_b);
    // 8. mlp hidden = gelu(h @ w1 + b1)
    sgemm_k<EPI_GELU><<<dim3(16, 256), 256>>>(xn, mlp_w1, mlph, MTOK, HID, CC, mlp_b1, nullptr);
    // 9. out = x1 + mlph @ w2 + b2
    sgemm_k<EPI_RES><<<dim3(4, 256), 256>>>(mlph, mlp_w2, out, MTOK, CC, HID, mlp_b2, x1);
}

// round 3
// speedup vs baseline: 1.4818x; 1.4818x over previous
#include <cuda_runtime.h>
#include <cuda_bf16.h>
#include <cstdint>

// ---------------- problem constants ----------------
#define BB 4
#define NN 8192
#define CC 512
#define HH 4
#define DD 128
#define HID 2048
#define MTOK (BB*NN)          // 32768
#define EPS 1e-5f
#define SCALE 0.08838834764831845f   // 128^-0.5

// ---------------- scratch ----------------
__device__ float g_xn  [(size_t)MTOK * CC];
__device__ float g_qkv [(size_t)MTOK * 3 * CC];
__device__ float g_attn[(size_t)MTOK * CC];
__device__ float g_x1  [(size_t)MTOK * CC];
__device__ float g_mlph[(size_t)MTOK * HID];
__device__ float g_ctxp[(size_t)32 * 16 * DD * DD];
__device__ float g_ctx [(size_t)16 * DD * DD];

// ---------------- helpers ----------------
__device__ __forceinline__ float to_tf32(float x) {
    uint32_t r;
    asm("cvt.rna.tf32.f32 %0, %1;" : "=r"(r) : "f"(x));
    return __uint_as_float(r);
}

__device__ __forceinline__ void mma_tf32(float* d, const float* a, const float* b) {
    asm volatile(
        "mma.sync.aligned.m16n8k8.row.col.f32.tf32.tf32.f32 "
        "{%0,%1,%2,%3}, {%4,%5,%6,%7}, {%8,%9}, {%0,%1,%2,%3};"
        : "+f"(d[0]), "+f"(d[1]), "+f"(d[2]), "+f"(d[3])
        : "r"(__float_as_uint(a[0])), "r"(__float_as_uint(a[1])),
          "r"(__float_as_uint(a[2])), "r"(__float_as_uint(a[3])),
          "r"(__float_as_uint(b[0])), "r"(__float_as_uint(b[1])));
}

// ---------------- LayerNorm over 512 ----------------
__global__ void ln_rows512(const float* __restrict__ x, float* __restrict__ y,
                           const float* __restrict__ w, const float* __restrict__ b) {
    int row = blockIdx.x;
    const float* xr = x + (size_t)row * CC;
    int t = threadIdx.x;
    float v0 = xr[t], v1 = xr[t + 256];
    float s = v0 + v1, s2 = v0 * v0 + v1 * v1;
#pragma unroll
    for (int o = 16; o > 0; o >>= 1) {
        s  += __shfl_xor_sync(0xffffffffu, s,  o);
        s2 += __shfl_xor_sync(0xffffffffu, s2, o);
    }
    __shared__ float sh[18];
    int wid = t >> 5, lane = t & 31;
    if (lane == 0) { sh[wid] = s; sh[wid + 8] = s2; }
    __syncthreads();
    if (t == 0) {
        float ts = 0.f, ts2 = 0.f;
#pragma unroll
        for (int i = 0; i < 8; i++) { ts += sh[i]; ts2 += sh[i + 8]; }
        float mu  = ts * (1.f / CC);
        float var = ts2 * (1.f / CC) - mu * mu;
        sh[16] = mu; sh[17] = rsqrtf(var + EPS);
    }
    __syncthreads();
    float mu = sh[16], inv = sh[17];
    float* yr = y + (size_t)row * CC;
    yr[t]       = (v0 - mu) * inv * w[t]       + b[t];
    yr[t + 256] = (v1 - mu) * inv * w[t + 256] + b[t + 256];
}

// ---------------- LayerNorm over 128 for k,v slices ----------------
__global__ void ln_kv(float* __restrict__ qkv,
                      const float* __restrict__ lnk_w, const float* __restrict__ lnk_b,
                      const float* __restrict__ lnv_w, const float* __restrict__ lnv_b) {
    int gwarp = (blockIdx.x * blockDim.x + threadIdx.x) >> 5;
    int lane  = threadIdx.x & 31;
    int bn   = gwarp >> 3;
    int rem  = gwarp & 7;
    int tsel = rem >> 2;
    int h    = rem & 3;
    size_t base = (size_t)bn * (3 * CC) + (size_t)(1 + tsel) * CC + (size_t)h * DD;
    float4 v = *(const float4*)(qkv + base + lane * 4);
    float s  = v.x + v.y + v.z + v.w;
    float s2 = v.x * v.x + v.y * v.y + v.z * v.z + v.w * v.w;
#pragma unroll
    for (int o = 16; o > 0; o >>= 1) {
        s  += __shfl_xor_sync(0xffffffffu, s,  o);
        s2 += __shfl_xor_sync(0xffffffffu, s2, o);
    }
    float mu  = s * (1.f / DD);
    float var = s2 * (1.f / DD) - mu * mu;
    float inv = rsqrtf(var + EPS);
    const float* w  = tsel ? lnv_w : lnk_w;
    const float* bb = tsel ? lnv_b : lnk_b;
    float4 wv = *(const float4*)(w  + lane * 4);
    float4 bv = *(const float4*)(bb + lane * 4);
    float4 o;
    o.x = (v.x - mu) * inv * wv.x + bv.x;
    o.y = (v.y - mu) * inv * wv.y + bv.y;
    o.z = (v.z - mu) * inv * wv.z + bv.z;
    o.w = (v.w - mu) * inv * wv.w + bv.w;
    *(float4*)(qkv + base + lane * 4) = o;
}

// ---------------- TF32 mma.sync GEMM: C[M,NTOT] = A[M,K] @ W[K,NTOT] --------
// block tile 128x128, BK=16, 8 warps (2x4), warp tile 64x32.
#define EPI_BIAS 0
#define EPI_GELU 1
#define EPI_RES  2

template <int NTOT, int K, int EPI>
__global__ __launch_bounds__(256, 2)
void mma_gemm(const float* __restrict__ A, const float* __restrict__ W,
              float* __restrict__ C, const float* __restrict__ bias,
              const float* __restrict__ res) {
    __shared__ float As[16][136];   // [k][m], stride 136 -> conflict-free fetch
    __shared__ float Bs[16][136];   // [k][n]
    const int tid = threadIdx.x;
    const int m0 = blockIdx.y * 128, n0 = blockIdx.x * 128;
    const int wid = tid >> 5, lane = tid & 31;
    const int wm0 = (wid >> 2) * 64;     // warp m offset (0 or 64)
    const int wn0 = (wid & 3) * 32;      // warp n offset
    const int g = lane >> 2, tq = lane & 3;

    float acc[4][4][4];
#pragma unroll
    for (int i = 0; i < 4; i++)
#pragma unroll
        for (int j = 0; j < 4; j++)
#pragma unroll
            for (int c = 0; c < 4; c++) acc[i][j][c] = 0.f;

    // global load indexing (2 float4 per thread per tile, each of A and B)
    const int ar0 = tid >> 2;           // A row for i=0 (0..63)
    const int akq = tid & 3;            // A k-quad
    const int bkr0 = tid >> 5;          // B k-row for i=0 (0..7)
    const int bnc = (tid & 31) * 4;     // B n col

    const int NTILES = K / 16;
    float4 pa[2], pb[2];
#pragma unroll
    for (int i = 0; i < 2; i++) {
        pa[i] = *(const float4*)(A + (size_t)(m0 + ar0 + i * 64) * K + akq * 4);
        pb[i] = *(const float4*)(W + (size_t)(bkr0 + i * 8) * NTOT + n0 + bnc);
    }

    for (int t = 0; t < NTILES; t++) {
        if (t > 0) __syncthreads();     // previous mma done reading smem
#pragma unroll
        for (int i = 0; i < 2; i++) {
            int arow = ar0 + i * 64;
            As[akq * 4 + 0][arow] = to_tf32(pa[i].x);
            As[akq * 4 + 1][arow] = to_tf32(pa[i].y);
            As[akq * 4 + 2][arow] = to_tf32(pa[i].z);
            As[akq * 4 + 3][arow] = to_tf32(pa[i].w);
            int bkr = bkr0 + i * 8;
            Bs[bkr][bnc + 0] = to_tf32(pb[i].x);
            Bs[bkr][bnc + 1] = to_tf32(pb[i].y);
            Bs[bkr][bnc + 2] = to_tf32(pb[i].z);
            Bs[bkr][bnc + 3] = to_tf32(pb[i].w);
        }
        __syncthreads();
        if (t + 1 < NTILES) {
#pragma unroll
            for (int i = 0; i < 2; i++) {
                pa[i] = *(const float4*)(A + (size_t)(m0 + ar0 + i * 64) * K + (t + 1) * 16 + akq * 4);
                pb[i] = *(const float4*)(W + (size_t)((t + 1) * 16 + bkr0 + i * 8) * NTOT + n0 + bnc);
            }
        }
#pragma unroll
        for (int ks = 0; ks < 2; ks++) {
            float a[4][4], b[4][2];
#pragma unroll
            for (int mt = 0; mt < 4; mt++) {
                int m = wm0 + mt * 16 + g;
                a[mt][0] = As[ks * 8 + tq][m];
                a[mt][1] = As[ks * 8 + tq][m + 8];
                a[mt][2] = As[ks * 8 + tq + 4][m];
                a[mt][3] = As[ks * 8 + tq + 4][m + 8];
            }
#pragma unroll
            for (int nt = 0; nt < 4; nt++) {
                int n = wn0 + nt * 8 + g;
                b[nt][0] = Bs[ks * 8 + tq][n];
                b[nt][1] = Bs[ks * 8 + tq + 4][n];
            }
#pragma unroll
            for (int mt = 0; mt < 4; mt++)
#pragma unroll
                for (int nt = 0; nt < 4; nt++)
                    mma_tf32(acc[mt][nt], a[mt], b[nt]);
        }
    }

    // ---- epilogue (fused bias / gelu / residual) ----
#pragma unroll
    for (int mt = 0; mt < 4; mt++) {
        int r0 = m0 + wm0 + mt * 16 + g;
#pragma unroll
        for (int nt = 0; nt < 4; nt++) {
            int cb = n0 + wn0 + nt * 8 + 2 * tq;
            float2 bv = *(const float2*)(bias + cb);
            float v0 = acc[mt][nt][0] + bv.x;
            float v1 = acc[mt][nt][1] + bv.y;
            float v2 = acc[mt][nt][2] + bv.x;
            float v3 = acc[mt][nt][3] + bv.y;
            if (EPI == EPI_GELU) {
                v0 *= normcdff(v0); v1 *= normcdff(v1);
                v2 *= normcdff(v2); v3 *= normcdff(v3);
            }
            size_t o0 = (size_t)r0 * NTOT + cb;
            size_t o1 = (size_t)(r0 + 8) * NTOT + cb;
            if (EPI == EPI_RES) {
                float2 r0v = *(const float2*)(res + o0);
                float2 r1v = *(const float2*)(res + o1);
                v0 += r0v.x; v1 += r0v.y; v2 += r1v.x; v3 += r1v.y;
            }
            float2 s0 = {v0, v1}, s1 = {v2, v3};
            *(float2*)(C + o0) = s0;
            *(float2*)(C + o1) = s1;
        }
    }
}

// ---------------- context partials ----------------
__global__ __launch_bounds__(256)
void ctx_partial(const float* __restrict__ qkv, float* __restrict__ ctxp) {
    int bh = blockIdx.x;
    int split = blockIdx.y;
    int b = bh >> 2, h = bh & 3;
    __shared__ float Ks[8][128];
    __shared__ float Vs[8][128];
    int tid = threadIdx.x;
    int tx = tid & 15, ty = tid >> 4;
    int lr = tid >> 5;
    int lc = (tid & 31) * 4;
    float acc[8][8];
#pragma unroll
    for (int i = 0; i < 8; i++)
#pragma unroll
        for (int j = 0; j < 8; j++) acc[i][j] = 0.f;

    int n0 = split * 256;
    for (int t = 0; t < 32; t++) {
        int n = n0 + t * 8 + lr;
        size_t base = ((size_t)b * NN + n) * (3 * CC) + CC + (size_t)h * DD;
        float4 kv = *(const float4*)(qkv + base + lc);
        float4 vv = *(const float4*)(qkv + base + CC + lc);
        __syncthreads();
        *(float4*)&Ks[lr][lc] = kv;
        *(float4*)&Vs[lr][lc] = vv;
        __syncthreads();
#pragma unroll
        for (int k = 0; k < 8; k++) {
            const float4* ap = (const float4*)&Ks[k][ty * 8];
            const float4* bp = (const float4*)&Vs[k][tx * 8];
            float4 a0 = ap[0], a1 = ap[1];
            float4 b0 = bp[0], b1 = bp[1];
            float a[8] = {a0.x, a0.y, a0.z, a0.w, a1.x, a1.y, a1.z, a1.w};
            float bb[8] = {b0.x, b0.y, b0.z, b0.w, b1.x, b1.y, b1.z, b1.w};
#pragma unroll
            for (int i = 0; i < 8; i++)
#pragma unroll
                for (int j = 0; j < 8; j++) acc[i][j] += a[i] * bb[j];
        }
    }
    float* outp = ctxp + ((size_t)split * 16 + bh) * (DD * DD);
#pragma unroll
    for (int i = 0; i < 8; i++)
#pragma unroll
        for (int j = 0; j < 8; j++)
            outp[(size_t)(ty * 8 + i) * DD + tx * 8 + j] = acc[i][j];
}

__global__ void reduce_ctx(const float* __restrict__ ctxp, float* __restrict__ ctx) {
    int i = blockIdx.x * blockDim.x + threadIdx.x;
    float s = 0.f;
#pragma unroll
    for (int sp = 0; sp < 32; sp++) s += ctxp[(size_t)sp * (16 * DD * DD) + i];
    ctx[i] = s;
}

// ---------------- attn = (q @ ctx) * SCALE ----------------
__global__ __launch_bounds__(256, 2)
void attn_k(const float* __restrict__ qkv, const float* __restrict__ ctx,
            float* __restrict__ attnb) {
    int mt = blockIdx.x;
    int bh = blockIdx.y;
    int b = bh >> 2, h = bh & 3;
    __shared__ float As[8][132];
    __shared__ float Bs[8][128];
    int tid = threadIdx.x;
    int tx = tid & 15, ty = tid >> 4;
    int arow = tid >> 1;
    int acol = (tid & 1) * 4;
    int brow = tid >> 5;
    int bcol = (tid & 31) * 4;

    size_t qbase = ((size_t)b * NN + mt * 128 + arow) * (3 * CC) + (size_t)h * DD;
    const float* cb = ctx + (size_t)bh * (DD * DD);

    float acc[8][8];
#pragma unroll
    for (int i = 0; i < 8; i++)
#pragma unroll
        for (int j = 0; j < 8; j++) acc[i][j] = 0.f;

    for (int t = 0; t < 16; t++) {
        float4 a4 = *(const float4*)(qkv + qbase + t * 8 + acol);
        float4 b4 = *(const float4*)(cb + (size_t)(t * 8 + brow) * DD + bcol);
        __syncthreads();
        As[acol + 0][arow] = a4.x; As[acol + 1][arow] = a4.y;
        As[acol + 2][arow] = a4.z; As[acol + 3][arow] = a4.w;
        *(float4*)&Bs[brow][bcol] = b4;
        __syncthreads();
#pragma unroll
        for (int k = 0; k < 8; k++) {
            const float4* ap = (const float4*)&As[k][ty * 8];
            const float4* bp = (const float4*)&Bs[k][tx * 8];
            float4 a0 = ap[0], a1 = ap[1];
            float4 b0 = bp[0], b1 = bp[1];
            float a[8] = {a0.x, a0.y, a0.z, a0.w, a1.x, a1.y, a1.z, a1.w};
            float bb[8] = {b0.x, b0.y, b0.z, b0.w, b1.x, b1.y, b1.z, b1.w};
#pragma unroll
            for (int i = 0; i < 8; i++)
#pragma unroll
                for (int j = 0; j < 8; j++) acc[i][j] += a[i] * bb[j];
        }
    }
#pragma unroll
    for (int i = 0; i < 8; i++) {
        size_t row = (size_t)b * NN + mt * 128 + ty * 8 + i;
        size_t off = row * CC + h * DD + tx * 8;
#pragma unroll
        for (int j = 0; j < 8; j++)
            attnb[off + j] = acc[i][j] * SCALE;
    }
}

// ---------------- launch ----------------
extern "C" void kernel_launch(void* const* d_in, const int* in_sizes, int n_in,
                              void* d_out, int out_size) {
    const float* x       = (const float*)d_in[0];
    const float* norm1_w = (const float*)d_in[1];
    const float* norm1_b = (const float*)d_in[2];
    const float* qkv_w   = (const float*)d_in[3];
    const float* qkv_b   = (const float*)d_in[4];
    const float* lnk_w   = (const float*)d_in[5];
    const float* lnk_b   = (const float*)d_in[6];
    const float* lnv_w   = (const float*)d_in[7];
    const float* lnv_b   = (const float*)d_in[8];
    const float* proj_w  = (const float*)d_in[9];
    const float* proj_b  = (const float*)d_in[10];
    const float* norm2_w = (const float*)d_in[11];
    const float* norm2_b = (const float*)d_in[12];
    const float* mlp_w1  = (const float*)d_in[13];
    const float* mlp_b1  = (const float*)d_in[14];
    const float* mlp_w2  = (const float*)d_in[15];
    const float* mlp_b2  = (const float*)d_in[16];
    float* out = (float*)d_out;

    float *xn, *qkv, *attnb, *x1, *mlph, *ctxp, *ctx;
    cudaGetSymbolAddress((void**)&xn,    g_xn);
    cudaGetSymbolAddress((void**)&qkv,   g_qkv);
    cudaGetSymbolAddress((void**)&attnb, g_attn);
    cudaGetSymbolAddress((void**)&x1,    g_x1);
    cudaGetSymbolAddress((void**)&mlph,  g_mlph);
    cudaGetSymbolAddress((void**)&ctxp,  g_ctxp);
    cudaGetSymbolAddress((void**)&ctx,   g_ctx);

    // 1. LN1
    ln_rows512<<<MTOK, 256>>>(x, xn, norm1_w, norm1_b);
    // 2. qkv = xn @ qkv_w + b   (tf32 mma.sync)
    mma_gemm<1536, 512, EPI_BIAS><<<dim3(12, 256), 256>>>(xn, qkv_w, qkv, qkv_b, nullptr);
    // 3. LN on k,v
    ln_kv<<<32768, 256>>>(qkv, lnk_w, lnk_b, lnv_w, lnv_b);
    // 4. context = k^T v
    ctx_partial<<<dim3(16, 32), 256>>>(qkv, ctxp);
    reduce_ctx<<<1024, 256>>>(ctxp, ctx);
    // 5. attn = q @ ctx * scale
    attn_k<<<dim3(64, 16), 256>>>(qkv, ctx, attnb);
    // 6. x1 = x + attn @ proj_w + b
    mma_gemm<512, 512, EPI_RES><<<dim3(4, 256), 256>>>(attnb, proj_w, x1, proj_b, x);
    // 7. LN2
    ln_rows512<<<MTOK, 256>>>(x1, xn, norm2_w, norm2_b);
    // 8. mlp hidden = gelu(h @ w1 + b1)
    mma_gemm<2048, 512, EPI_GELU><<<dim3(16, 256), 256>>>(xn, mlp_w1, mlph, mlp_b1, nullptr);
    // 9. out = x1 + mlph @ w2 + b2
    mma_gemm<512, 2048, EPI_RES><<<dim3(4, 256), 256>>>(mlph, mlp_w2, out, mlp_b2, x1);
}

// round 4
// speedup vs baseline: 2.2150x; 1.4948x over previous
#include <cuda_runtime.h>
#include <cuda_fp16.h>
#include <cuda_bf16.h>
#include <cstdint>

// ---------------- problem constants ----------------
#define BB 4
#define NN 8192
#define CC 512
#define HH 4
#define DD 128
#define HID 2048
#define MTOK (BB*NN)          // 32768
#define EPS 1e-5f
#define SCALE 0.08838834764831845f   // 128^-0.5
#define CSPLIT 64

// ---------------- scratch ----------------
__device__ float g_xn  [(size_t)MTOK * CC];
__device__ float g_qkv [(size_t)MTOK * 3 * CC];
__device__ float g_attn[(size_t)MTOK * CC];
__device__ float g_x1  [(size_t)MTOK * CC];
__device__ float g_mlph[(size_t)MTOK * HID];
__device__ float g_ctxp[(size_t)CSPLIT * 16 * DD * DD];
__device__ float g_ctx [(size_t)16 * DD * DD];

// ---------------- helpers ----------------
__device__ __forceinline__ unsigned pkh2(float x, float y) {
    __half2 h = __floats2half2_rn(x, y);
    return *reinterpret_cast<unsigned*>(&h);
}

__device__ __forceinline__ void mma_f16(float* d, const unsigned* a, const unsigned* b) {
    asm volatile(
        "mma.sync.aligned.m16n8k16.row.col.f32.f16.f16.f32 "
        "{%0,%1,%2,%3}, {%4,%5,%6,%7}, {%8,%9}, {%0,%1,%2,%3};"
        : "+f"(d[0]), "+f"(d[1]), "+f"(d[2]), "+f"(d[3])
        : "r"(a[0]), "r"(a[1]), "r"(a[2]), "r"(a[3]), "r"(b[0]), "r"(b[1]));
}

// ---------------- LayerNorm over 512 ----------------
__global__ void ln_rows512(const float* __restrict__ x, float* __restrict__ y,
                           const float* __restrict__ w, const float* __restrict__ b) {
    int row = blockIdx.x;
    const float* xr = x + (size_t)row * CC;
    int t = threadIdx.x;
    float v0 = xr[t], v1 = xr[t + 256];
    float s = v0 + v1, s2 = v0 * v0 + v1 * v1;
#pragma unroll
    for (int o = 16; o > 0; o >>= 1) {
        s  += __shfl_xor_sync(0xffffffffu, s,  o);
        s2 += __shfl_xor_sync(0xffffffffu, s2, o);
    }
    __shared__ float sh[18];
    int wid = t >> 5, lane = t & 31;
    if (lane == 0) { sh[wid] = s; sh[wid + 8] = s2; }
    __syncthreads();
    if (t == 0) {
        float ts = 0.f, ts2 = 0.f;
#pragma unroll
        for (int i = 0; i < 8; i++) { ts += sh[i]; ts2 += sh[i + 8]; }
        float mu  = ts * (1.f / CC);
        float var = ts2 * (1.f / CC) - mu * mu;
        sh[16] = mu; sh[17] = rsqrtf(var + EPS);
    }
    __syncthreads();
    float mu = sh[16], inv = sh[17];
    float* yr = y + (size_t)row * CC;
    yr[t]       = (v0 - mu) * inv * w[t]       + b[t];
    yr[t + 256] = (v1 - mu) * inv * w[t + 256] + b[t + 256];
}

// ---------------- LayerNorm over 128 for k,v slices ----------------
__global__ void ln_kv(float* __restrict__ qkv,
                      const float* __restrict__ lnk_w, const float* __restrict__ lnk_b,
                      const float* __restrict__ lnv_w, const float* __restrict__ lnv_b) {
    int gwarp = (blockIdx.x * blockDim.x + threadIdx.x) >> 5;
    int lane  = threadIdx.x & 31;
    int bn   = gwarp >> 3;
    int rem  = gwarp & 7;
    int tsel = rem >> 2;
    int h    = rem & 3;
    size_t base = (size_t)bn * (3 * CC) + (size_t)(1 + tsel) * CC + (size_t)h * DD;
    float4 v = *(const float4*)(qkv + base + lane * 4);
    float s  = v.x + v.y + v.z + v.w;
    float s2 = v.x * v.x + v.y * v.y + v.z * v.z + v.w * v.w;
#pragma unroll
    for (int o = 16; o > 0; o >>= 1) {
        s  += __shfl_xor_sync(0xffffffffu, s,  o);
        s2 += __shfl_xor_sync(0xffffffffu, s2, o);
    }
    float mu  = s * (1.f / DD);
    float var = s2 * (1.f / DD) - mu * mu;
    float inv = rsqrtf(var + EPS);
    const float* w  = tsel ? lnv_w : lnk_w;
    const float* bb = tsel ? lnv_b : lnk_b;
    float4 wv = *(const float4*)(w  + lane * 4);
    float4 bv = *(const float4*)(bb + lane * 4);
    float4 o;
    o.x = (v.x - mu) * inv * wv.x + bv.x;
    o.y = (v.y - mu) * inv * wv.y + bv.y;
    o.z = (v.z - mu) * inv * wv.z + bv.z;
    o.w = (v.w - mu) * inv * wv.w + bv.w;
    *(float4*)(qkv + base + lane * 4) = o;
}

// ---------------- FP16 mma.sync GEMM: C[M,NTOT] = A[M,K] @ W[K,NTOT] --------
// block tile 128x128, BK=32, 8 warps (2x4), warp tile 64x32.
// Double-buffered SMEM (half2 packed along k), one __syncthreads per K-tile.
#define EPI_BIAS 0
#define EPI_GELU 1
#define EPI_RES  2

template <int NTOT, int K, int EPI>
__global__ __launch_bounds__(256, 2)
void mma_gemm(const float* __restrict__ A, const float* __restrict__ W,
              float* __restrict__ C, const float* __restrict__ bias,
              const float* __restrict__ res) {
    // As2[s][p][m]: halves (k=2p, 2p+1) at row m. stride 137 -> conflict-light
    // Bs2[s][p][n]: halves (k=2p, 2p+1) at col n. stride 136 -> conflict-free
    __shared__ unsigned As2[2][16][137];
    __shared__ alignas(16) unsigned Bs2[2][16][136];

    const int tid = threadIdx.x;
    const int m0 = blockIdx.y * 128, n0 = blockIdx.x * 128;
    const int wid = tid >> 5, lane = tid & 31;
    const int wm0 = (wid >> 2) * 64;
    const int wn0 = (wid & 3) * 32;
    const int g = lane >> 2, tq = lane & 3;

    float acc[4][4][4];
#pragma unroll
    for (int i = 0; i < 4; i++)
#pragma unroll
        for (int j = 0; j < 4; j++)
#pragma unroll
            for (int c = 0; c < 4; c++) acc[i][j][c] = 0.f;

    const int NT = K / 32;
    float4 pa[4], pb0[2], pb1[2];

    auto gload = [&](int t) {
#pragma unroll
        for (int i = 0; i < 4; i++) {
            int idx = tid + i * 256;
            int arow = idx >> 3, akq = idx & 7;
            pa[i] = *(const float4*)(A + (size_t)(m0 + arow) * K + t * 32 + akq * 4);
        }
#pragma unroll
        for (int i = 0; i < 2; i++) {
            int idx = tid + i * 256;
            int bp = idx >> 5, bc = (idx & 31) * 4;
            pb0[i] = *(const float4*)(W + (size_t)(t * 32 + 2 * bp)     * NTOT + n0 + bc);
            pb1[i] = *(const float4*)(W + (size_t)(t * 32 + 2 * bp + 1) * NTOT + n0 + bc);
        }
    };
    auto sstore = [&](int s) {
#pragma unroll
        for (int i = 0; i < 4; i++) {
            int idx = tid + i * 256;
            int arow = idx >> 3, akq = idx & 7;
            As2[s][akq * 2][arow]     = pkh2(pa[i].x, pa[i].y);
            As2[s][akq * 2 + 1][arow] = pkh2(pa[i].z, pa[i].w);
        }
#pragma unroll
        for (int i = 0; i < 2; i++) {
            int idx = tid + i * 256;
            int bp = idx >> 5, bc = (idx & 31) * 4;
            uint4 u;
            u.x = pkh2(pb0[i].x, pb1[i].x);
            u.y = pkh2(pb0[i].y, pb1[i].y);
            u.z = pkh2(pb0[i].z, pb1[i].z);
            u.w = pkh2(pb0[i].w, pb1[i].w);
            *(uint4*)&Bs2[s][bp][bc] = u;
        }
    };

    gload(0);
    sstore(0);
    __syncthreads();

    for (int t = 0; t < NT; t++) {
        const int s = t & 1;
        if (t + 1 < NT) gload(t + 1);   // LDG issued early, consumed after mma
#pragma unroll
        for (int ks = 0; ks < 2; ks++) {
            unsigned a[4][4], b[4][2];
#pragma unroll
            for (int mt = 0; mt < 4; mt++) {
                int m = wm0 + mt * 16 + g;
                a[mt][0] = As2[s][ks * 8 + tq][m];
                a[mt][1] = As2[s][ks * 8 + tq][m + 8];
                a[mt][2] = As2[s][ks * 8 + tq + 4][m];
                a[mt][3] = As2[s][ks * 8 + tq + 4][m + 8];
            }
#pragma unroll
            for (int nt = 0; nt < 4; nt++) {
                int n = wn0 + nt * 8 + g;
                b[nt][0] = Bs2[s][ks * 8 + tq][n];
                b[nt][1] = Bs2[s][ks * 8 + tq + 4][n];
            }
#pragma unroll
            for (int mt = 0; mt < 4; mt++)
#pragma unroll
                for (int nt = 0; nt < 4; nt++)
                    mma_f16(acc[mt][nt], a[mt], b[nt]);
        }
        if (t + 1 < NT) {
            sstore(s ^ 1);
            __syncthreads();
        }
    }

    // ---- epilogue (fused bias / gelu / residual) ----
#pragma unroll
    for (int mt = 0; mt < 4; mt++) {
        int r0 = m0 + wm0 + mt * 16 + g;
#pragma unroll
        for (int nt = 0; nt < 4; nt++) {
            int cb = n0 + wn0 + nt * 8 + 2 * tq;
            float2 bv = *(const float2*)(bias + cb);
            float v0 = acc[mt][nt][0] + bv.x;
            float v1 = acc[mt][nt][1] + bv.y;
            float v2 = acc[mt][nt][2] + bv.x;
            float v3 = acc[mt][nt][3] + bv.y;
            if (EPI == EPI_GELU) {
                v0 *= normcdff(v0); v1 *= normcdff(v1);
                v2 *= normcdff(v2); v3 *= normcdff(v3);
            }
            size_t o0 = (size_t)r0 * NTOT + cb;
            size_t o1 = (size_t)(r0 + 8) * NTOT + cb;
            if (EPI == EPI_RES) {
                float2 r0v = *(const float2*)(res + o0);
                float2 r1v = *(const float2*)(res + o1);
                v0 += r0v.x; v1 += r0v.y; v2 += r1v.x; v3 += r1v.y;
            }
            float2 s0 = {v0, v1}, s1 = {v2, v3};
            *(float2*)(C + o0) = s0;
            *(float2*)(C + o1) = s1;
        }
    }
}

// ---------------- context partials: split over CSPLIT chunks of 128 rows ----
__global__ __launch_bounds__(256)
void ctx_partial(const float* __restrict__ qkv, float* __restrict__ ctxp) {
    int bh = blockIdx.x;
    int split = blockIdx.y;
    int b = bh >> 2, h = bh & 3;
    __shared__ float Ks[8][128];
    __shared__ float Vs[8][128];
    int tid = threadIdx.x;
    int tx = tid & 15, ty = tid >> 4;
    int lr = tid >> 5;
    int lc = (tid & 31) * 4;
    float acc[8][8];
#pragma unroll
    for (int i = 0; i < 8; i++)
#pragma unroll
        for (int j = 0; j < 8; j++) acc[i][j] = 0.f;

    int n0 = split * (NN / CSPLIT);
    for (int t = 0; t < (NN / CSPLIT) / 8; t++) {
        int n = n0 + t * 8 + lr;
        size_t base = ((size_t)b * NN + n) * (3 * CC) + CC + (size_t)h * DD;
        float4 kv = *(const float4*)(qkv + base + lc);
        float4 vv = *(const float4*)(qkv + base + CC + lc);
        __syncthreads();
        *(float4*)&Ks[lr][lc] = kv;
        *(float4*)&Vs[lr][lc] = vv;
        __syncthreads();
#pragma unroll
        for (int k = 0; k < 8; k++) {
            const float4* ap = (const float4*)&Ks[k][ty * 8];
            const float4* bp = (const float4*)&Vs[k][tx * 8];
            float4 a0 = ap[0], a1 = ap[1];
            float4 b0 = bp[0], b1 = bp[1];
            float a[8] = {a0.x, a0.y, a0.z, a0.w, a1.x, a1.y, a1.z, a1.w};
            float bb[8] = {b0.x, b0.y, b0.z, b0.w, b1.x, b1.y, b1.z, b1.w};
#pragma unroll
            for (int i = 0; i < 8; i++)
#pragma unroll
                for (int j = 0; j < 8; j++) acc[i][j] += a[i] * bb[j];
        }
    }
    float* outp = ctxp + ((size_t)split * 16 + bh) * (DD * DD);
#pragma unroll
    for (int i = 0; i < 8; i++)
#pragma unroll
        for (int j = 0; j < 8; j++)
            outp[(size_t)(ty * 8 + i) * DD + tx * 8 + j] = acc[i][j];
}

__global__ void reduce_ctx(const float* __restrict__ ctxp, float* __restrict__ ctx) {
    int i = blockIdx.x * blockDim.x + threadIdx.x;
    float s = 0.f;
#pragma unroll
    for (int sp = 0; sp < CSPLIT; sp++) s += ctxp[(size_t)sp * (16 * DD * DD) + i];
    ctx[i] = s;
}

// ---------------- attn = (q @ ctx) * SCALE ----------------
__global__ __launch_bounds__(256, 2)
void attn_k(const float* __restrict__ qkv, const float* __restrict__ ctx,
            float* __restrict__ attnb) {
    int mt = blockIdx.x;
    int bh = blockIdx.y;
    int b = bh >> 2, h = bh & 3;
    __shared__ float As[8][132];
    __shared__ float Bs[8][128];
    int tid = threadIdx.x;
    int tx = tid & 15, ty = tid >> 4;
    int arow = tid >> 1;
    int acol = (tid & 1) * 4;
    int brow = tid >> 5;
    int bcol = (tid & 31) * 4;

    size_t qbase = ((size_t)b * NN + mt * 128 + arow) * (3 * CC) + (size_t)h * DD;
    const float* cb = ctx + (size_t)bh * (DD * DD);

    float acc[8][8];
#pragma unroll
    for (int i = 0; i < 8; i++)
#pragma unroll
        for (int j = 0; j < 8; j++) acc[i][j] = 0.f;

    for (int t = 0; t < 16; t++) {
        float4 a4 = *(const float4*)(qkv + qbase + t * 8 + acol);
        float4 b4 = *(const float4*)(cb + (size_t)(t * 8 + brow) * DD + bcol);
        __syncthreads();
        As[acol + 0][arow] = a4.x; As[acol + 1][arow] = a4.y;
        As[acol + 2][arow] = a4.z; As[acol + 3][arow] = a4.w;
        *(float4*)&Bs[brow][bcol] = b4;
        __syncthreads();
#pragma unroll
        for (int k = 0; k < 8; k++) {
            const float4* ap = (const float4*)&As[k][ty * 8];
            const float4* bp = (const float4*)&Bs[k][tx * 8];
            float4 a0 = ap[0], a1 = ap[1];
            float4 b0 = bp[0], b1 = bp[1];
            float a[8] = {a0.x, a0.y, a0.z, a0.w, a1.x, a1.y, a1.z, a1.w};
            float bb[8] = {b0.x, b0.y, b0.z, b0.w, b1.x, b1.y, b1.z, b1.w};
#pragma unroll
            for (int i = 0; i < 8; i++)
#pragma unroll
                for (int j = 0; j < 8; j++) acc[i][j] += a[i] * bb[j];
        }
    }
#pragma unroll
    for (int i = 0; i < 8; i++) {
        size_t row = (size_t)b * NN + mt * 128 + ty * 8 + i;
        size_t off = row * CC + h * DD + tx * 8;
#pragma unroll
        for (int j = 0; j < 8; j++)
            attnb[off + j] = acc[i][j] * SCALE;
    }
}

// ---------------- launch ----------------
extern "C" void kernel_launch(void* const* d_in, const int* in_sizes, int n_in,
                              void* d_out, int out_size) {
    const float* x       = (const float*)d_in[0];
    const float* norm1_w = (const float*)d_in[1];
    const float* norm1_b = (const float*)d_in[2];
    const float* qkv_w   = (const float*)d_in[3];
    const float* qkv_b   = (const float*)d_in[4];
    const float* lnk_w   = (const float*)d_in[5];
    const float* lnk_b   = (const float*)d_in[6];
    const float* lnv_w   = (const float*)d_in[7];
    const float* lnv_b   = (const float*)d_in[8];
    const float* proj_w  = (const float*)d_in[9];
    const float* proj_b  = (const float*)d_in[10];
    const float* norm2_w = (const float*)d_in[11];
    const float* norm2_b = (const float*)d_in[12];
    const float* mlp_w1  = (const float*)d_in[13];
    const float* mlp_b1  = (const float*)d_in[14];
    const float* mlp_w2  = (const float*)d_in[15];
    const float* mlp_b2  = (const float*)d_in[16];
    float* out = (float*)d_out;

    float *xn, *qkv, *attnb, *x1, *mlph, *ctxp, *ctx;
    cudaGetSymbolAddress((void**)&xn,    g_xn);
    cudaGetSymbolAddress((void**)&qkv,   g_qkv);
    cudaGetSymbolAddress((void**)&attnb, g_attn);
    cudaGetSymbolAddress((void**)&x1,    g_x1);
    cudaGetSymbolAddress((void**)&mlph,  g_mlph);
    cudaGetSymbolAddress((void**)&ctxp,  g_ctxp);
    cudaGetSymbolAddress((void**)&ctx,   g_ctx);

    // 1. LN1
    ln_rows512<<<MTOK, 256>>>(x, xn, norm1_w, norm1_b);
    // 2. qkv = xn @ qkv_w + b   (fp16 mma.sync, fp32 accum)
    mma_gemm<1536, 512, EPI_BIAS><<<dim3(12, 256), 256>>>(xn, qkv_w, qkv, qkv_b, nullptr);
    // 3. LN on k,v
    ln_kv<<<32768, 256>>>(qkv, lnk_w, lnk_b, lnv_w, lnv_b);
    // 4. context = k^T v
    ctx_partial<<<dim3(16, CSPLIT), 256>>>(qkv, ctxp);
    reduce_ctx<<<1024, 256>>>(ctxp, ctx);
    // 5. attn = q @ ctx * scale
    attn_k<<<dim3(64, 16), 256>>>(qkv, ctx, attnb);
    // 6. x1 = x + attn @ proj_w + b
    mma_gemm<512, 512, EPI_RES><<<dim3(4, 256), 256>>>(attnb, proj_w, x1, proj_b, x);
    // 7. LN2
    ln_rows512<<<MTOK, 256>>>(x1, xn, norm2_w, norm2_b);
    // 8. mlp hidden = gelu(h @ w1 + b1)
    mma_gemm<2048, 512, EPI_GELU><<<dim3(16, 256), 256>>>(xn, mlp_w1, mlph, mlp_b1, nullptr);
    // 9. out = x1 + mlph @ w2 + b2
    mma_gemm<512, 2048, EPI_RES><<<dim3(4, 256), 256>>>(mlph, mlp_w2, out, mlp_b2, x1);
}

// round 5
// speedup vs baseline: 4.4583x; 2.0128x over previous
#include <cuda_runtime.h>
#include <cuda_fp16.h>
#include <cstdint>

// ---------------- problem constants ----------------
#define BB 4
#define NN 8192
#define CC 512
#define DD 128
#define HID 2048
#define MTOK 32768
#define EPS 1e-5f
#define SCALE 0.08838834764831845f   // 128^-0.5
#define CSPLIT 32

// ---------------- scratch ----------------
__device__ float  g_qkv [(size_t)MTOK * 1536];        // fp32 qkv (pre-LN k,v; LN stats)
__device__ float  g_x1  [(size_t)MTOK * CC];          // fp32 residual
__device__ float  g_ctxp[(size_t)CSPLIT * 16 * DD * DD];
__device__ __half g_xh   [(size_t)MTOK * CC];         // LN1/LN2 out (fp16)
__device__ __half g_qkvh [(size_t)MTOK * 1536];       // fp16 q (gemm epi) + LN'd k,v
__device__ __half g_attnh[(size_t)MTOK * CC];
__device__ __half g_mlphh[(size_t)MTOK * HID];
__device__ __half g_ctxh [(size_t)16 * DD * DD];
__device__ __half g_wh   [(size_t)3145728];           // all weights fp16

#define WH_QKV  0
#define WH_PROJ 786432
#define WH_MLP1 1048576
#define WH_MLP2 2097152

// ---------------- ptx helpers ----------------
__device__ __forceinline__ uint32_t smem_u32(const void* p) {
    uint32_t r;
    asm("{ .reg .u64 t; cvta.to.shared.u64 t, %1; cvt.u32.u64 %0, t; }" : "=r"(r) : "l"(p));
    return r;
}
__device__ __forceinline__ void mma_f16(float* d, const unsigned* a, const unsigned* b) {
    asm volatile(
        "mma.sync.aligned.m16n8k16.row.col.f32.f16.f16.f32 "
        "{%0,%1,%2,%3}, {%4,%5,%6,%7}, {%8,%9}, {%0,%1,%2,%3};"
        : "+f"(d[0]), "+f"(d[1]), "+f"(d[2]), "+f"(d[3])
        : "r"(a[0]), "r"(a[1]), "r"(a[2]), "r"(a[3]), "r"(b[0]), "r"(b[1]));
}
__device__ __forceinline__ void ldsm4(unsigned& r0, unsigned& r1, unsigned& r2, unsigned& r3, uint32_t a) {
    asm volatile("ldmatrix.sync.aligned.m8n8.x4.shared.b16 {%0,%1,%2,%3}, [%4];"
                 : "=r"(r0), "=r"(r1), "=r"(r2), "=r"(r3) : "r"(a));
}
__device__ __forceinline__ void ldsm4t(unsigned& r0, unsigned& r1, unsigned& r2, unsigned& r3, uint32_t a) {
    asm volatile("ldmatrix.sync.aligned.m8n8.x4.trans.shared.b16 {%0,%1,%2,%3}, [%4];"
                 : "=r"(r0), "=r"(r1), "=r"(r2), "=r"(r3) : "r"(a));
}
__device__ __forceinline__ void cpa16(uint32_t dst, const void* src) {
    asm volatile("cp.async.cg.shared.global [%0], [%1], 16;" :: "r"(dst), "l"(src));
}
#define CP_COMMIT() asm volatile("cp.async.commit_group;" ::: "memory")
#define CP_WAIT2()  asm volatile("cp.async.wait_group 2;" ::: "memory")

// ---------------- fp32 -> fp16 convert ----------------
__global__ void f2h(const float* __restrict__ s, __half* __restrict__ d, int n) {
    int i = (blockIdx.x * 256 + threadIdx.x) * 4;
    if (i < n) {
        float4 v = *(const float4*)(s + i);
        __half2 h0 = __floats2half2_rn(v.x, v.y), h1 = __floats2half2_rn(v.z, v.w);
        uint2 u; u.x = *(unsigned*)&h0; u.y = *(unsigned*)&h1;
        *(uint2*)(d + i) = u;
    }
}

// ---------------- LayerNorm over 512 (fp32 in, fp16 out) ----------------
__global__ void ln_rows512(const float* __restrict__ x, __half* __restrict__ y,
                           const float* __restrict__ w, const float* __restrict__ b) {
    int row = blockIdx.x;
    const float* xr = x + (size_t)row * CC;
    int t = threadIdx.x;
    float2 v = *(const float2*)(xr + 2 * t);
    float s = v.x + v.y, s2 = v.x * v.x + v.y * v.y;
#pragma unroll
    for (int o = 16; o > 0; o >>= 1) {
        s  += __shfl_xor_sync(0xffffffffu, s,  o);
        s2 += __shfl_xor_sync(0xffffffffu, s2, o);
    }
    __shared__ float sh[18];
    int wid = t >> 5, lane = t & 31;
    if (lane == 0) { sh[wid] = s; sh[wid + 8] = s2; }
    __syncthreads();
    if (t == 0) {
        float ts = 0.f, ts2 = 0.f;
#pragma unroll
        for (int i = 0; i < 8; i++) { ts += sh[i]; ts2 += sh[i + 8]; }
        float mu  = ts * (1.f / CC);
        float var = ts2 * (1.f / CC) - mu * mu;
        sh[16] = mu; sh[17] = rsqrtf(var + EPS);
    }
    __syncthreads();
    float mu = sh[16], inv = sh[17];
    float2 wv = *(const float2*)(w + 2 * t);
    float2 bv = *(const float2*)(b + 2 * t);
    __half2 o = __floats2half2_rn((v.x - mu) * inv * wv.x + bv.x,
                                  (v.y - mu) * inv * wv.y + bv.y);
    *(__half2*)(y + (size_t)row * CC + 2 * t) = o;
}

// ---------------- LN over 128 for k,v (fp32 in, fp16 out into qkvh) --------
__global__ void ln_kv(const float* __restrict__ qkv, __half* __restrict__ qkvh,
                      const float* __restrict__ lnk_w, const float* __restrict__ lnk_b,
                      const float* __restrict__ lnv_w, const float* __restrict__ lnv_b) {
    int gwarp = (blockIdx.x * blockDim.x + threadIdx.x) >> 5;
    int lane  = threadIdx.x & 31;
    int bn   = gwarp >> 3;
    int rem  = gwarp & 7;
    int tsel = rem >> 2;
    int h    = rem & 3;
    size_t base = (size_t)bn * 1536 + (size_t)(1 + tsel) * CC + (size_t)h * DD;
    float4 v = *(const float4*)(qkv + base + lane * 4);
    float s  = v.x + v.y + v.z + v.w;
    float s2 = v.x * v.x + v.y * v.y + v.z * v.z + v.w * v.w;
#pragma unroll
    for (int o = 16; o > 0; o >>= 1) {
        s  += __shfl_xor_sync(0xffffffffu, s,  o);
        s2 += __shfl_xor_sync(0xffffffffu, s2, o);
    }
    float mu  = s * (1.f / DD);
    float var = s2 * (1.f / DD) - mu * mu;
    float inv = rsqrtf(var + EPS);
    const float* w  = tsel ? lnv_w : lnk_w;
    const float* bb = tsel ? lnv_b : lnk_b;
    float4 wv = *(const float4*)(w  + lane * 4);
    float4 bv = *(const float4*)(bb + lane * 4);
    __half2 h0 = __floats2half2_rn((v.x - mu) * inv * wv.x + bv.x,
                                   (v.y - mu) * inv * wv.y + bv.y);
    __half2 h1 = __floats2half2_rn((v.z - mu) * inv * wv.z + bv.z,
                                   (v.w - mu) * inv * wv.w + bv.w);
    uint2 u; u.x = *(unsigned*)&h0; u.y = *(unsigned*)&h1;
    *(uint2*)(qkvh + base + lane * 4) = u;
}

// ---------------- pipelined fp16 GEMM: C[M,NTOT] = A[M,K] @ W[K,NTOT] -------
// tile 128x256, BK=32, 4-stage cp.async, ldmatrix, 8 warps (2x4), warp 64x64.
#define EPI_BIAS 0
#define EPI_GELU 1
#define EPI_RES  2
// smem halves: As[4][128][40] then Bs[4][32][264]
#define HSM_BYTES ((4*128*40 + 4*32*264) * 2)

template <int NTOT, int K, int WF32, int H16, int EPI>
__global__ __launch_bounds__(256, 1)
void hgemm(const __half* __restrict__ A, const __half* __restrict__ W,
           float* __restrict__ C, __half* __restrict__ Ch,
           const float* __restrict__ bias, const float* __restrict__ res) {
    extern __shared__ __half hsm[];
    const int tid = threadIdx.x;
    const int m0 = blockIdx.y * 128, n0 = blockIdx.x * 256;
    const int lane = tid & 31, wid = tid >> 5;
    const int wm0 = (wid >> 2) * 64, wn0 = (wid & 3) * 64;
    const int g = lane >> 2, tq = lane & 3;
    const uint32_t sb = smem_u32(hsm);

    float acc[4][8][4];
#pragma unroll
    for (int i = 0; i < 4; i++)
#pragma unroll
        for (int j = 0; j < 8; j++)
#pragma unroll
            for (int c = 0; c < 4; c++) acc[i][j][c] = 0.f;

    // cp.async indexing
    const int am  = tid >> 2;         // A row 0..63 (+64)
    const int akg = tid & 3;          // A k-granule
    const int bk  = tid >> 5;         // B k-row 0..7 (+8i)
    const int bg  = tid & 31;         // B n-granule
    const __half* aptr  = A + (size_t)(m0 + am) * K + akg * 8;
    const __half* aptr2 = A + (size_t)(m0 + am + 64) * K + akg * 8;
    const __half* wptr  = W + (size_t)bk * NTOT + n0 + bg * 8;
    const uint32_t adst = sb + (uint32_t)(am * 40 + akg * 8) * 2;
    const uint32_t bdst = sb + (uint32_t)(20480 + bk * 264 + bg * 8) * 2;

    const int NT = K / 32;
#pragma unroll 1
    for (int p = 0; p < 3; p++) {
        uint32_t ad = adst + (uint32_t)(p * 5120) * 2;
        cpa16(ad, aptr + (size_t)p * 32);
        cpa16(ad + 64 * 40 * 2, aptr2 + (size_t)p * 32);
        uint32_t bd = bdst + (uint32_t)(p * 8448) * 2;
        const __half* wp = wptr + (size_t)p * 32 * NTOT;
#pragma unroll
        for (int i = 0; i < 4; i++)
            cpa16(bd + (uint32_t)(i * 8 * 264) * 2, wp + (size_t)i * 8 * NTOT);
        CP_COMMIT();
    }

    const int a_r = lane & 15;
    const int a_c = (lane >> 4) * 8;

#pragma unroll 1
    for (int t = 0; t < NT; t++) {
        CP_WAIT2();
        __syncthreads();
        if (t + 3 < NT) {
            const int sn = (t + 3) & 3;
            uint32_t ad = adst + (uint32_t)(sn * 5120) * 2;
            cpa16(ad, aptr + (size_t)(t + 3) * 32);
            cpa16(ad + 64 * 40 * 2, aptr2 + (size_t)(t + 3) * 32);
            uint32_t bd = bdst + (uint32_t)(sn * 8448) * 2;
            const __half* wp = wptr + (size_t)(t + 3) * 32 * NTOT;
#pragma unroll
            for (int i = 0; i < 4; i++)
                cpa16(bd + (uint32_t)(i * 8 * 264) * 2, wp + (size_t)i * 8 * NTOT);
        }
        CP_COMMIT();
        const int s = t & 3;
        const uint32_t as_ = sb + (uint32_t)(s * 5120) * 2;
        const uint32_t bs_ = sb + (uint32_t)(20480 + s * 8448) * 2;
#pragma unroll
        for (int ks = 0; ks < 2; ks++) {
            unsigned af[4][4], bf[8][2];
#pragma unroll
            for (int mt = 0; mt < 4; mt++)
                ldsm4(af[mt][0], af[mt][1], af[mt][2], af[mt][3],
                      as_ + (uint32_t)((wm0 + mt * 16 + a_r) * 40 + ks * 16 + a_c) * 2);
#pragma unroll
            for (int nq = 0; nq < 4; nq++)
                ldsm4t(bf[2 * nq][0], bf[2 * nq][1], bf[2 * nq + 1][0], bf[2 * nq + 1][1],
                       bs_ + (uint32_t)((ks * 16 + a_r) * 264 + wn0 + nq * 16 + a_c) * 2);
#pragma unroll
            for (int mt = 0; mt < 4; mt++)
#pragma unroll
                for (int nt = 0; nt < 8; nt++)
                    mma_f16(acc[mt][nt], af[mt], bf[nt]);
        }
    }

    // ---- epilogue ----
#pragma unroll
    for (int mt = 0; mt < 4; mt++) {
        int r0 = m0 + wm0 + mt * 16 + g;
#pragma unroll
        for (int nt = 0; nt < 8; nt++) {
            int cb = n0 + wn0 + nt * 8 + 2 * tq;
            float2 bv = *(const float2*)(bias + cb);
            float v0 = acc[mt][nt][0] + bv.x;
            float v1 = acc[mt][nt][1] + bv.y;
            float v2 = acc[mt][nt][2] + bv.x;
            float v3 = acc[mt][nt][3] + bv.y;
            if (EPI == EPI_GELU) {
                v0 *= normcdff(v0); v1 *= normcdff(v1);
                v2 *= normcdff(v2); v3 *= normcdff(v3);
            }
            size_t o0 = (size_t)r0 * NTOT + cb;
            size_t o1 = (size_t)(r0 + 8) * NTOT + cb;
            if (EPI == EPI_RES) {
                float2 r0v = *(const float2*)(res + o0);
                float2 r1v = *(const float2*)(res + o1);
                v0 += r0v.x; v1 += r0v.y; v2 += r1v.x; v3 += r1v.y;
            }
            if (WF32) {
                float2 s0 = {v0, v1}, s1 = {v2, v3};
                *(float2*)(C + o0) = s0;
                *(float2*)(C + o1) = s1;
            }
            if (H16) {
                if (H16 >= NTOT || cb < H16) {
                    __half2 h0 = __floats2half2_rn(v0, v1);
                    __half2 h1 = __floats2half2_rn(v2, v3);
                    *(__half2*)(Ch + o0) = h0;
                    *(__half2*)(Ch + o1) = h1;
                }
            }
        }
    }
}

// ---------------- context partials via mma: ctxp = k^T v ----------------
__global__ __launch_bounds__(256, 2)
void ctx_mma(const __half* __restrict__ qkvh, float* __restrict__ ctxp) {
    __shared__ __half Kt[32][136];
    __shared__ __half Vt[32][136];
    const int bh = blockIdx.x, split = blockIdx.y;
    const int b = bh >> 2, h = bh & 3;
    const int tid = threadIdx.x, lane = tid & 31, wid = tid >> 5;
    const int wm0 = (wid >> 2) * 64, wn0 = (wid & 3) * 32;
    const int g = lane >> 2, tq = lane & 3;
    const uint32_t kb = smem_u32(Kt), vb = smem_u32(Vt);

    float acc[4][4][4];
#pragma unroll
    for (int i = 0; i < 4; i++)
#pragma unroll
        for (int j = 0; j < 4; j++)
#pragma unroll
            for (int c = 0; c < 4; c++) acc[i][j][c] = 0.f;

    const int arA = lane & 7, acA = (lane >> 3) & 1, asA = (lane >> 4) & 1;
    const int a_r = lane & 15, a_c = (lane >> 4) * 8;

    for (int ch = 0; ch < 8; ch++) {
        int nb = split * 256 + ch * 32;
        if (ch) __syncthreads();
#pragma unroll
        for (int i = 0; i < 2; i++) {
            int idx = tid + i * 256;
            int row = idx >> 4, gc = idx & 15;
            size_t src = ((size_t)(b * NN + nb + row)) * 1536 + (size_t)h * DD + gc * 8;
            *(uint4*)&Kt[row][gc * 8] = *(const uint4*)(qkvh + src + 512);
            *(uint4*)&Vt[row][gc * 8] = *(const uint4*)(qkvh + src + 1024);
        }
        __syncthreads();
#pragma unroll
        for (int ks = 0; ks < 2; ks++) {
            unsigned af[4][4], bf[4][2];
#pragma unroll
            for (int mt = 0; mt < 4; mt++)
                ldsm4t(af[mt][0], af[mt][1], af[mt][2], af[mt][3],
                       kb + (uint32_t)((ks * 16 + arA + asA * 8) * 136 +
                                       wm0 + mt * 16 + acA * 8) * 2);
#pragma unroll
            for (int nq = 0; nq < 2; nq++)
                ldsm4t(bf[2 * nq][0], bf[2 * nq][1], bf[2 * nq + 1][0], bf[2 * nq + 1][1],
                       vb + (uint32_t)((ks * 16 + a_r) * 136 + wn0 + nq * 16 + a_c) * 2);
#pragma unroll
            for (int mt = 0; mt < 4; mt++)
#pragma unroll
                for (int nt = 0; nt < 4; nt++)
                    mma_f16(acc[mt][nt], af[mt], bf[nt]);
        }
    }
    float* outp = ctxp + ((size_t)split * 16 + bh) * (DD * DD);
#pragma unroll
    for (int mt = 0; mt < 4; mt++) {
        int d = wm0 + mt * 16 + g;
#pragma unroll
        for (int nt = 0; nt < 4; nt++) {
            int e = wn0 + nt * 8 + 2 * tq;
            float2 s0 = {acc[mt][nt][0], acc[mt][nt][1]};
            float2 s1 = {acc[mt][nt][2], acc[mt][nt][3]};
            *(float2*)(outp + (size_t)d * DD + e) = s0;
            *(float2*)(outp + (size_t)(d + 8) * DD + e) = s1;
        }
    }
}

__global__ void reduce_ctx(const float* __restrict__ ctxp, __half* __restrict__ ctxh) {
    int i = blockIdx.x * blockDim.x + threadIdx.x;
    float s = 0.f;
#pragma unroll
    for (int sp = 0; sp < CSPLIT; sp++) s += ctxp[(size_t)sp * (16 * DD * DD) + i];
    ctxh[i] = __float2half(s * SCALE);
}

// ---------------- attn = q @ (ctx*scale) via mma, fp16 out ----------------
#define ASM_BYTES (2 * 128 * 136 * 2)
__global__ __launch_bounds__(256, 2)
void attn_mma(const __half* __restrict__ qkvh, const __half* __restrict__ ctxh,
              __half* __restrict__ attnh) {
    extern __shared__ __half asmem[];
    __half* Qs = asmem;
    __half* Cs = asmem + 128 * 136;
    const int tile = blockIdx.x, bh = blockIdx.y;
    const int b = bh >> 2, h = bh & 3;
    const int tid = threadIdx.x, lane = tid & 31, wid = tid >> 5;
    const int wm0 = (wid >> 2) * 64, wn0 = (wid & 3) * 32;
    const int g = lane >> 2, tq = lane & 3;

#pragma unroll
    for (int i = 0; i < 8; i++) {
        int idx = tid + i * 256;
        int row = idx >> 4, gc = idx & 15;
        *(uint4*)&Qs[row * 136 + gc * 8] =
            *(const uint4*)(qkvh + ((size_t)(b * NN + tile * 128 + row)) * 1536 +
                            (size_t)h * DD + gc * 8);
        *(uint4*)&Cs[row * 136 + gc * 8] =
            *(const uint4*)(ctxh + (size_t)bh * (DD * DD) + (size_t)row * DD + gc * 8);
    }
    __syncthreads();

    float acc[4][4][4];
#pragma unroll
    for (int i = 0; i < 4; i++)
#pragma unroll
        for (int j = 0; j < 4; j++)
#pragma unroll
            for (int c = 0; c < 4; c++) acc[i][j][c] = 0.f;

    const uint32_t qb = smem_u32(Qs), cb2 = smem_u32(Cs);
    const int a_r = lane & 15, a_c = (lane >> 4) * 8;

#pragma unroll
    for (int ks = 0; ks < 8; ks++) {
        unsigned af[4][4], bf[4][2];
#pragma unroll
        for (int mt = 0; mt < 4; mt++)
            ldsm4(af[mt][0], af[mt][1], af[mt][2], af[mt][3],
                  qb + (uint32_t)((wm0 + mt * 16 + a_r) * 136 + ks * 16 + a_c) * 2);
#pragma unroll
        for (int nq = 0; nq < 2; nq++)
            ldsm4t(bf[2 * nq][0], bf[2 * nq][1], bf[2 * nq + 1][0], bf[2 * nq + 1][1],
                   cb2 + (uint32_t)((ks * 16 + a_r) * 136 + wn0 + nq * 16 + a_c) * 2);
#pragma unroll
        for (int mt = 0; mt < 4; mt++)
#pragma unroll
            for (int nt = 0; nt < 4; nt++)
                mma_f16(acc[mt][nt], af[mt], bf[nt]);
    }

#pragma unroll
    for (int mt = 0; mt < 4; mt++) {
        size_t r0 = (size_t)(b * NN + tile * 128 + wm0 + mt * 16 + g);
#pragma unroll
        for (int nt = 0; nt < 4; nt++) {
            int col = h * DD + wn0 + nt * 8 + 2 * tq;
            __half2 h0 = __floats2half2_rn(acc[mt][nt][0], acc[mt][nt][1]);
            __half2 h1 = __floats2half2_rn(acc[mt][nt][2], acc[mt][nt][3]);
            *(__half2*)(attnh + r0 * CC + col) = h0;
            *(__half2*)(attnh + (r0 + 8) * CC + col) = h1;
        }
    }
}

// ---------------- launch ----------------
extern "C" void kernel_launch(void* const* d_in, const int* in_sizes, int n_in,
                              void* d_out, int out_size) {
    const float* x       = (const float*)d_in[0];
    const float* norm1_w = (const float*)d_in[1];
    const float* norm1_b = (const float*)d_in[2];
    const float* qkv_w   = (const float*)d_in[3];
    const float* qkv_b   = (const float*)d_in[4];
    const float* lnk_w   = (const float*)d_in[5];
    const float* lnk_b   = (const float*)d_in[6];
    const float* lnv_w   = (const float*)d_in[7];
    const float* lnv_b   = (const float*)d_in[8];
    const float* proj_w  = (const float*)d_in[9];
    const float* proj_b  = (const float*)d_in[10];
    const float* norm2_w = (const float*)d_in[11];
    const float* norm2_b = (const float*)d_in[12];
    const float* mlp_w1  = (const float*)d_in[13];
    const float* mlp_b1  = (const float*)d_in[14];
    const float* mlp_w2  = (const float*)d_in[15];
    const float* mlp_b2  = (const float*)d_in[16];
    float* out = (float*)d_out;

    float  *qkv, *x1, *ctxp;
    __half *xh, *qkvh, *attnh, *mlphh, *ctxh, *wh;
    cudaGetSymbolAddress((void**)&qkv,   g_qkv);
    cudaGetSymbolAddress((void**)&x1,    g_x1);
    cudaGetSymbolAddress((void**)&ctxp,  g_ctxp);
    cudaGetSymbolAddress((void**)&xh,    g_xh);
    cudaGetSymbolAddress((void**)&qkvh,  g_qkvh);
    cudaGetSymbolAddress((void**)&attnh, g_attnh);
    cudaGetSymbolAddress((void**)&mlphh, g_mlphh);
    cudaGetSymbolAddress((void**)&ctxh,  g_ctxh);
    cudaGetSymbolAddress((void**)&wh,    g_wh);

    cudaFuncSetAttribute(hgemm<1536, 512, 1, 512, EPI_BIAS>,
                         cudaFuncAttributeMaxDynamicSharedMemorySize, HSM_BYTES);
    cudaFuncSetAttribute(hgemm<512, 512, 1, 0, EPI_RES>,
                         cudaFuncAttributeMaxDynamicSharedMemorySize, HSM_BYTES);
    cudaFuncSetAttribute(hgemm<2048, 512, 0, 2048, EPI_GELU>,
                         cudaFuncAttributeMaxDynamicSharedMemorySize, HSM_BYTES);
    cudaFuncSetAttribute(hgemm<512, 2048, 1, 0, EPI_RES>,
                         cudaFuncAttributeMaxDynamicSharedMemorySize, HSM_BYTES);
    cudaFuncSetAttribute(attn_mma,
                         cudaFuncAttributeMaxDynamicSharedMemorySize, ASM_BYTES);

    // 0. weights -> fp16
    f2h<<<768, 256>>>(qkv_w,  wh + WH_QKV,  786432);
    f2h<<<256, 256>>>(proj_w, wh + WH_PROJ, 262144);
    f2h<<<1024, 256>>>(mlp_w1, wh + WH_MLP1, 1048576);
    f2h<<<1024, 256>>>(mlp_w2, wh + WH_MLP2, 1048576);

    // 1. LN1 -> fp16
    ln_rows512<<<MTOK, 256>>>(x, xh, norm1_w, norm1_b);
    // 2. qkv = xn @ qkv_w + b  (fp32 out for ln_kv; fp16 q copy)
    hgemm<1536, 512, 1, 512, EPI_BIAS><<<dim3(6, 256), 256, HSM_BYTES>>>(
        xh, wh + WH_QKV, qkv, qkvh, qkv_b, nullptr);
    // 3. LN k,v -> fp16 into qkvh
    ln_kv<<<32768, 256>>>(qkv, qkvh, lnk_w, lnk_b, lnv_w, lnv_b);
    // 4. context = k^T v (tensor-core split-K) ; reduce * SCALE -> fp16
    ctx_mma<<<dim3(16, CSPLIT), 256>>>(qkvh, ctxp);
    reduce_ctx<<<1024, 256>>>(ctxp, ctxh);
    // 5. attn = q @ ctx  -> fp16
    attn_mma<<<dim3(64, 16), 256, ASM_BYTES>>>(qkvh, ctxh, attnh);
    // 6. x1 = x + attn @ proj_w + b  (fp32)
    hgemm<512, 512, 1, 0, EPI_RES><<<dim3(2, 256), 256, HSM_BYTES>>>(
        attnh, wh + WH_PROJ, x1, nullptr, proj_b, x);
    // 7. LN2 -> fp16
    ln_rows512<<<MTOK, 256>>>(x1, xh, norm2_w, norm2_b);
    // 8. mlp hidden = gelu(h @ w1 + b1)  (fp16 only)
    hgemm<2048, 512, 0, 2048, EPI_GELU><<<dim3(8, 256), 256, HSM_BYTES>>>(
        xh, wh + WH_MLP1, nullptr, mlphh, mlp_b1, nullptr);
    // 9. out = x1 + mlph @ w2 + b2  (fp32)
    hgemm<512, 2048, 1, 0, EPI_RES><<<dim3(2, 256), 256, HSM_BYTES>>>(
        mlphh, wh + WH_MLP2, out, nullptr, mlp_b2, x1);
}

// round 6
// speedup vs baseline: 4.6911x; 1.0522x over previous
#include <cuda_runtime.h>
#include <cuda_fp16.h>
#include <cstdint>

// ---------------- problem constants ----------------
#define BB 4
#define NN 8192
#define CC 512
#define DD 128
#define HID 2048
#define MTOK 32768
#define EPS 1e-5f
#define SCALE 0.08838834764831845f   // 128^-0.5
#define CSPLIT 16

// ---------------- scratch ----------------
__device__ float  g_x1  [(size_t)MTOK * CC];          // fp32 residual
__device__ float  g_ctxp[(size_t)CSPLIT * 16 * DD * DD];
__device__ __half g_xh   [(size_t)MTOK * CC];         // LN1/LN2 out (fp16)
__device__ __half g_qkvh [(size_t)MTOK * 1536];       // fp16 q + LN'd k,v
__device__ __half g_attnh[(size_t)MTOK * CC];
__device__ __half g_mlphh[(size_t)MTOK * HID];
__device__ __half g_ctxh [(size_t)16 * DD * DD];
__device__ __half g_wh   [(size_t)3145728];           // all weights fp16

#define WH_QKV  0
#define WH_PROJ 786432
#define WH_MLP1 1048576
#define WH_MLP2 2097152

// ---------------- ptx helpers ----------------
__device__ __forceinline__ uint32_t smem_u32(const void* p) {
    uint32_t r;
    asm("{ .reg .u64 t; cvta.to.shared.u64 t, %1; cvt.u32.u64 %0, t; }" : "=r"(r) : "l"(p));
    return r;
}
__device__ __forceinline__ void mma_f16(float* d, const unsigned* a, const unsigned* b) {
    asm volatile(
        "mma.sync.aligned.m16n8k16.row.col.f32.f16.f16.f32 "
        "{%0,%1,%2,%3}, {%4,%5,%6,%7}, {%8,%9}, {%0,%1,%2,%3};"
        : "+f"(d[0]), "+f"(d[1]), "+f"(d[2]), "+f"(d[3])
        : "r"(a[0]), "r"(a[1]), "r"(a[2]), "r"(a[3]), "r"(b[0]), "r"(b[1]));
}
__device__ __forceinline__ void ldsm4(unsigned& r0, unsigned& r1, unsigned& r2, unsigned& r3, uint32_t a) {
    asm volatile("ldmatrix.sync.aligned.m8n8.x4.shared.b16 {%0,%1,%2,%3}, [%4];"
                 : "=r"(r0), "=r"(r1), "=r"(r2), "=r"(r3) : "r"(a));
}
__device__ __forceinline__ void ldsm4t(unsigned& r0, unsigned& r1, unsigned& r2, unsigned& r3, uint32_t a) {
    asm volatile("ldmatrix.sync.aligned.m8n8.x4.trans.shared.b16 {%0,%1,%2,%3}, [%4];"
                 : "=r"(r0), "=r"(r1), "=r"(r2), "=r"(r3) : "r"(a));
}
__device__ __forceinline__ void cpa16(uint32_t dst, const void* src) {
    asm volatile("cp.async.cg.shared.global [%0], [%1], 16;" :: "r"(dst), "l"(src));
}
#define CP_COMMIT() asm volatile("cp.async.commit_group;" ::: "memory")
#define CP_WAIT2()  asm volatile("cp.async.wait_group 2;" ::: "memory")

// ---------------- fused fp32 -> fp16 weight convert ----------------
__global__ void f2h_all(const float* __restrict__ a, const float* __restrict__ b,
                        const float* __restrict__ c, const float* __restrict__ d,
                        __half* __restrict__ out) {
    int i = (blockIdx.x * 256 + threadIdx.x) * 4;   // < 3145728
    const float* src; int off;
    if (i < 786432)       { src = a; off = i; }
    else if (i < 1048576) { src = b; off = i - 786432; }
    else if (i < 2097152) { src = c; off = i - 1048576; }
    else                  { src = d; off = i - 2097152; }
    float4 v = *(const float4*)(src + off);
    __half2 h0 = __floats2half2_rn(v.x, v.y), h1 = __floats2half2_rn(v.z, v.w);
    uint2 u; u.x = *(unsigned*)&h0; u.y = *(unsigned*)&h1;
    *(uint2*)(out + i) = u;
}

// ---------------- LayerNorm over 512 (fp32 in, fp16 out) ----------------
__global__ void ln_rows512(const float* __restrict__ x, __half* __restrict__ y,
                           const float* __restrict__ w, const float* __restrict__ b) {
    int row = blockIdx.x;
    const float* xr = x + (size_t)row * CC;
    int t = threadIdx.x;
    float2 v = *(const float2*)(xr + 2 * t);
    float s = v.x + v.y, s2 = v.x * v.x + v.y * v.y;
#pragma unroll
    for (int o = 16; o > 0; o >>= 1) {
        s  += __shfl_xor_sync(0xffffffffu, s,  o);
        s2 += __shfl_xor_sync(0xffffffffu, s2, o);
    }
    __shared__ float sh[18];
    int wid = t >> 5, lane = t & 31;
    if (lane == 0) { sh[wid] = s; sh[wid + 8] = s2; }
    __syncthreads();
    if (t == 0) {
        float ts = 0.f, ts2 = 0.f;
#pragma unroll
        for (int i = 0; i < 8; i++) { ts += sh[i]; ts2 += sh[i + 8]; }
        float mu  = ts * (1.f / CC);
        float var = ts2 * (1.f / CC) - mu * mu;
        sh[16] = mu; sh[17] = rsqrtf(var + EPS);
    }
    __syncthreads();
    float mu = sh[16], inv = sh[17];
    float2 wv = *(const float2*)(w + 2 * t);
    float2 bv = *(const float2*)(b + 2 * t);
    __half2 o = __floats2half2_rn((v.x - mu) * inv * wv.x + bv.x,
                                  (v.y - mu) * inv * wv.y + bv.y);
    *(__half2*)(y + (size_t)row * CC + 2 * t) = o;
}

// ---------------- pipelined fp16 GEMM: C[M,NTOT] = A[M,K] @ W[K,NTOT] -------
// tile 128x256, BK=32, 4-stage cp.async, ldmatrix, 8 warps (2x4), warp 64x64.
// EPI_QKV: bias + (for k/v sections) fused per-head LayerNorm, fp16-only out.
#define EPI_BIAS 0
#define EPI_GELU 1
#define EPI_RES  2
#define EPI_QKV  3
#define HSM_BYTES ((4*128*40 + 4*32*264) * 2)

template <int NTOT, int K, int WF32, int H16, int EPI>
__global__ __launch_bounds__(256, 1)
void hgemm(const __half* __restrict__ A, const __half* __restrict__ W,
           float* __restrict__ C, __half* __restrict__ Ch,
           const float* __restrict__ bias, const float* __restrict__ res,
           const float* __restrict__ lnk_w, const float* __restrict__ lnk_b,
           const float* __restrict__ lnv_w, const float* __restrict__ lnv_b) {
    extern __shared__ __half hsm[];
    const int tid = threadIdx.x;
    const int m0 = blockIdx.y * 128, n0 = blockIdx.x * 256;
    const int lane = tid & 31, wid = tid >> 5;
    const int wm0 = (wid >> 2) * 64, wn0 = (wid & 3) * 64;
    const int g = lane >> 2, tq = lane & 3;
    const uint32_t sb = smem_u32(hsm);

    float acc[4][8][4];
#pragma unroll
    for (int i = 0; i < 4; i++)
#pragma unroll
        for (int j = 0; j < 8; j++)
#pragma unroll
            for (int c = 0; c < 4; c++) acc[i][j][c] = 0.f;

    const int am  = tid >> 2;
    const int akg = tid & 3;
    const int bk  = tid >> 5;
    const int bg  = tid & 31;
    const __half* aptr  = A + (size_t)(m0 + am) * K + akg * 8;
    const __half* aptr2 = A + (size_t)(m0 + am + 64) * K + akg * 8;
    const __half* wptr  = W + (size_t)bk * NTOT + n0 + bg * 8;
    const uint32_t adst = sb + (uint32_t)(am * 40 + akg * 8) * 2;
    const uint32_t bdst = sb + (uint32_t)(20480 + bk * 264 + bg * 8) * 2;

    const int NT = K / 32;
#pragma unroll 1
    for (int p = 0; p < 3; p++) {
        uint32_t ad = adst + (uint32_t)(p * 5120) * 2;
        cpa16(ad, aptr + (size_t)p * 32);
        cpa16(ad + 64 * 40 * 2, aptr2 + (size_t)p * 32);
        uint32_t bd = bdst + (uint32_t)(p * 8448) * 2;
        const __half* wp = wptr + (size_t)p * 32 * NTOT;
#pragma unroll
        for (int i = 0; i < 4; i++)
            cpa16(bd + (uint32_t)(i * 8 * 264) * 2, wp + (size_t)i * 8 * NTOT);
        CP_COMMIT();
    }

    const int a_r = lane & 15;
    const int a_c = (lane >> 4) * 8;

#pragma unroll 1
    for (int t = 0; t < NT; t++) {
        CP_WAIT2();
        __syncthreads();
        if (t + 3 < NT) {
            const int sn = (t + 3) & 3;
            uint32_t ad = adst + (uint32_t)(sn * 5120) * 2;
            cpa16(ad, aptr + (size_t)(t + 3) * 32);
            cpa16(ad + 64 * 40 * 2, aptr2 + (size_t)(t + 3) * 32);
            uint32_t bd = bdst + (uint32_t)(sn * 8448) * 2;
            const __half* wp = wptr + (size_t)(t + 3) * 32 * NTOT;
#pragma unroll
            for (int i = 0; i < 4; i++)
                cpa16(bd + (uint32_t)(i * 8 * 264) * 2, wp + (size_t)i * 8 * NTOT);
        }
        CP_COMMIT();
        const int s = t & 3;
        const uint32_t as_ = sb + (uint32_t)(s * 5120) * 2;
        const uint32_t bs_ = sb + (uint32_t)(20480 + s * 8448) * 2;
#pragma unroll
        for (int ks = 0; ks < 2; ks++) {
            unsigned af[4][4], bf[8][2];
#pragma unroll
            for (int mt = 0; mt < 4; mt++)
                ldsm4(af[mt][0], af[mt][1], af[mt][2], af[mt][3],
                      as_ + (uint32_t)((wm0 + mt * 16 + a_r) * 40 + ks * 16 + a_c) * 2);
#pragma unroll
            for (int nq = 0; nq < 4; nq++)
                ldsm4t(bf[2 * nq][0], bf[2 * nq][1], bf[2 * nq + 1][0], bf[2 * nq + 1][1],
                       bs_ + (uint32_t)((ks * 16 + a_r) * 264 + wn0 + nq * 16 + a_c) * 2);
#pragma unroll
            for (int mt = 0; mt < 4; mt++)
#pragma unroll
                for (int nt = 0; nt < 8; nt++)
                    mma_f16(acc[mt][nt], af[mt], bf[nt]);
        }
    }

    if (EPI == EPI_QKV) {
        // ---- bias ----
#pragma unroll
        for (int mt = 0; mt < 4; mt++)
#pragma unroll
            for (int nt = 0; nt < 8; nt++) {
                int cb = n0 + wn0 + nt * 8 + 2 * tq;
                float2 bv = *(const float2*)(bias + cb);
                acc[mt][nt][0] += bv.x; acc[mt][nt][1] += bv.y;
                acc[mt][nt][2] += bv.x; acc[mt][nt][3] += bv.y;
            }
        // ---- fused LN for k (x∈{2,3}) / v (x∈{4,5}) sections ----
        if (blockIdx.x >= 2) {
            const float* lw = (blockIdx.x < 4) ? lnk_w : lnv_w;
            const float* lb = (blockIdx.x < 4) ? lnk_b : lnv_b;
            float* red = (float*)hsm;       // [2 heads][128 rows][2 halves][2]
            float ps[4][2], ps2[4][2];
#pragma unroll
            for (int mt = 0; mt < 4; mt++)
#pragma unroll
                for (int h2 = 0; h2 < 2; h2++) {
                    float s = 0.f, s2 = 0.f;
#pragma unroll
                    for (int nt = 0; nt < 8; nt++) {
                        float a = acc[mt][nt][2 * h2], b = acc[mt][nt][2 * h2 + 1];
                        s += a + b; s2 += a * a + b * b;
                    }
                    ps[mt][h2] = s; ps2[mt][h2] = s2;
                }
#pragma unroll
            for (int off = 1; off < 4; off <<= 1)
#pragma unroll
                for (int mt = 0; mt < 4; mt++)
#pragma unroll
                    for (int h2 = 0; h2 < 2; h2++) {
                        ps[mt][h2]  += __shfl_xor_sync(0xffffffffu, ps[mt][h2],  off);
                        ps2[mt][h2] += __shfl_xor_sync(0xffffffffu, ps2[mt][h2], off);
                    }
            __syncthreads();                 // mainloop smem reads done
            const int head = (wid >> 1) & 1, half = wid & 1;
            if (tq == 0) {
#pragma unroll
                for (int mt = 0; mt < 4; mt++)
#pragma unroll
                    for (int h2 = 0; h2 < 2; h2++) {
                        int row = wm0 + mt * 16 + g + 8 * h2;
                        int idx = ((head * 128 + row) * 2 + half) * 2;
                        red[idx] = ps[mt][h2]; red[idx + 1] = ps2[mt][h2];
                    }
            }
            __syncthreads();
#pragma unroll
            for (int mt = 0; mt < 4; mt++) {
                float mu[2], inv[2];
#pragma unroll
                for (int h2 = 0; h2 < 2; h2++) {
                    int row = wm0 + mt * 16 + g + 8 * h2;
                    int i0 = ((head * 128 + row) * 2) * 2;
                    float s  = red[i0] + red[i0 + 2];
                    float s2 = red[i0 + 1] + red[i0 + 3];
                    float m = s * (1.f / 128);
                    mu[h2] = m;
                    inv[h2] = rsqrtf(s2 * (1.f / 128) - m * m + EPS);
                }
#pragma unroll
                for (int nt = 0; nt < 8; nt++) {
                    int ch = (wid & 1) * 64 + nt * 8 + 2 * tq;   // col within head
                    float2 lwv = *(const float2*)(lw + ch);
                    float2 lbv = *(const float2*)(lb + ch);
                    acc[mt][nt][0] = (acc[mt][nt][0] - mu[0]) * inv[0] * lwv.x + lbv.x;
                    acc[mt][nt][1] = (acc[mt][nt][1] - mu[0]) * inv[0] * lwv.y + lbv.y;
                    acc[mt][nt][2] = (acc[mt][nt][2] - mu[1]) * inv[1] * lwv.x + lbv.x;
                    acc[mt][nt][3] = (acc[mt][nt][3] - mu[1]) * inv[1] * lwv.y + lbv.y;
                }
            }
        }
        // ---- fp16 store ----
#pragma unroll
        for (int mt = 0; mt < 4; mt++) {
            int r0 = m0 + wm0 + mt * 16 + g;
#pragma unroll
            for (int nt = 0; nt < 8; nt++) {
                int cb = n0 + wn0 + nt * 8 + 2 * tq;
                __half2 h0 = __floats2half2_rn(acc[mt][nt][0], acc[mt][nt][1]);
                __half2 h1 = __floats2half2_rn(acc[mt][nt][2], acc[mt][nt][3]);
                *(__half2*)(Ch + (size_t)r0 * NTOT + cb) = h0;
                *(__half2*)(Ch + (size_t)(r0 + 8) * NTOT + cb) = h1;
            }
        }
        return;
    }

    // ---- generic epilogue ----
#pragma unroll
    for (int mt = 0; mt < 4; mt++) {
        int r0 = m0 + wm0 + mt * 16 + g;
#pragma unroll
        for (int nt = 0; nt < 8; nt++) {
            int cb = n0 + wn0 + nt * 8 + 2 * tq;
            float2 bv = *(const float2*)(bias + cb);
            float v0 = acc[mt][nt][0] + bv.x;
            float v1 = acc[mt][nt][1] + bv.y;
            float v2 = acc[mt][nt][2] + bv.x;
            float v3 = acc[mt][nt][3] + bv.y;
            if (EPI == EPI_GELU) {
                v0 *= normcdff(v0); v1 *= normcdff(v1);
                v2 *= normcdff(v2); v3 *= normcdff(v3);
            }
            size_t o0 = (size_t)r0 * NTOT + cb;
            size_t o1 = (size_t)(r0 + 8) * NTOT + cb;
            if (EPI == EPI_RES) {
                float2 r0v = *(const float2*)(res + o0);
                float2 r1v = *(const float2*)(res + o1);
                v0 += r0v.x; v1 += r0v.y; v2 += r1v.x; v3 += r1v.y;
            }
            if (WF32) {
                float2 s0 = {v0, v1}, s1 = {v2, v3};
                *(float2*)(C + o0) = s0;
                *(float2*)(C + o1) = s1;
            }
            if (H16) {
                __half2 h0 = __floats2half2_rn(v0, v1);
                __half2 h1 = __floats2half2_rn(v2, v3);
                *(__half2*)(Ch + o0) = h0;
                *(__half2*)(Ch + o1) = h1;
            }
        }
    }
}

// ---------------- context partials via mma: ctxp = k^T v ----------------
__global__ __launch_bounds__(256, 2)
void ctx_mma(const __half* __restrict__ qkvh, float* __restrict__ ctxp) {
    __shared__ __half Kt[32][136];
    __shared__ __half Vt[32][136];
    const int bh = blockIdx.x, split = blockIdx.y;
    const int b = bh >> 2, h = bh & 3;
    const int tid = threadIdx.x, lane = tid & 31, wid = tid >> 5;
    const int wm0 = (wid >> 2) * 64, wn0 = (wid & 3) * 32;
    const int g = lane >> 2, tq = lane & 3;
    const uint32_t kb = smem_u32(Kt), vb = smem_u32(Vt);

    float acc[4][4][4];
#pragma unroll
    for (int i = 0; i < 4; i++)
#pragma unroll
        for (int j = 0; j < 4; j++)
#pragma unroll
            for (int c = 0; c < 4; c++) acc[i][j][c] = 0.f;

    const int arA = lane & 7, acA = (lane >> 3) & 1, asA = (lane >> 4) & 1;
    const int a_r = lane & 15, a_c = (lane >> 4) * 8;

    for (int ch = 0; ch < (NN / CSPLIT) / 32; ch++) {
        int nb = split * (NN / CSPLIT) + ch * 32;
        if (ch) __syncthreads();
#pragma unroll
        for (int i = 0; i < 2; i++) {
            int idx = tid + i * 256;
            int row = idx >> 4, gc = idx & 15;
            size_t src = ((size_t)(b * NN + nb + row)) * 1536 + (size_t)h * DD + gc * 8;
            *(uint4*)&Kt[row][gc * 8] = *(const uint4*)(qkvh + src + 512);
            *(uint4*)&Vt[row][gc * 8] = *(const uint4*)(qkvh + src + 1024);
        }
        __syncthreads();
#pragma unroll
        for (int ks = 0; ks < 2; ks++) {
            unsigned af[4][4], bf[4][2];
#pragma unroll
            for (int mt = 0; mt < 4; mt++)
                ldsm4t(af[mt][0], af[mt][1], af[mt][2], af[mt][3],
                       kb + (uint32_t)((ks * 16 + arA + asA * 8) * 136 +
                                       wm0 + mt * 16 + acA * 8) * 2);
#pragma unroll
            for (int nq = 0; nq < 2; nq++)
                ldsm4t(bf[2 * nq][0], bf[2 * nq][1], bf[2 * nq + 1][0], bf[2 * nq + 1][1],
                       vb + (uint32_t)((ks * 16 + a_r) * 136 + wn0 + nq * 16 + a_c) * 2);
#pragma unroll
            for (int mt = 0; mt < 4; mt++)
#pragma unroll
                for (int nt = 0; nt < 4; nt++)
                    mma_f16(acc[mt][nt], af[mt], bf[nt]);
        }
    }
    float* outp = ctxp + ((size_t)split * 16 + bh) * (DD * DD);
#pragma unroll
    for (int mt = 0; mt < 4; mt++) {
        int d = wm0 + mt * 16 + g;
#pragma unroll
        for (int nt = 0; nt < 4; nt++) {
            int e = wn0 + nt * 8 + 2 * tq;
            float2 s0 = {acc[mt][nt][0], acc[mt][nt][1]};
            float2 s1 = {acc[mt][nt][2], acc[mt][nt][3]};
            *(float2*)(outp + (size_t)d * DD + e) = s0;
            *(float2*)(outp + (size_t)(d + 8) * DD + e) = s1;
        }
    }
}

__global__ void reduce_ctx(const float* __restrict__ ctxp, __half* __restrict__ ctxh) {
    int i = blockIdx.x * blockDim.x + threadIdx.x;
    float s = 0.f;
#pragma unroll
    for (int sp = 0; sp < CSPLIT; sp++) s += ctxp[(size_t)sp * (16 * DD * DD) + i];
    ctxh[i] = __float2half(s * SCALE);
}

// ---------------- attn = q @ (ctx*scale) via mma, fp16 out ----------------
#define ASM_BYTES (2 * 128 * 136 * 2)
__global__ __launch_bounds__(256, 2)
void attn_mma(const __half* __restrict__ qkvh, const __half* __restrict__ ctxh,
              __half* __restrict__ attnh) {
    extern __shared__ __half asmem[];
    __half* Qs = asmem;
    __half* Cs = asmem + 128 * 136;
    const int tile = blockIdx.x, bh = blockIdx.y;
    const int b = bh >> 2, h = bh & 3;
    const int tid = threadIdx.x, lane = tid & 31, wid = tid >> 5;
    const int wm0 = (wid >> 2) * 64, wn0 = (wid & 3) * 32;
    const int g = lane >> 2, tq = lane & 3;

#pragma unroll
    for (int i = 0; i < 8; i++) {
        int idx = tid + i * 256;
        int row = idx >> 4, gc = idx & 15;
        *(uint4*)&Qs[row * 136 + gc * 8] =
            *(const uint4*)(qkvh + ((size_t)(b * NN + tile * 128 + row)) * 1536 +
                            (size_t)h * DD + gc * 8);
        *(uint4*)&Cs[row * 136 + gc * 8] =
            *(const uint4*)(ctxh + (size_t)bh * (DD * DD) + (size_t)row * DD + gc * 8);
    }
    __syncthreads();

    float acc[4][4][4];
#pragma unroll
    for (int i = 0; i < 4; i++)
#pragma unroll
        for (int j = 0; j < 4; j++)
#pragma unroll
            for (int c = 0; c < 4; c++) acc[i][j][c] = 0.f;

    const uint32_t qb = smem_u32(Qs), cb2 = smem_u32(Cs);
    const int a_r = lane & 15, a_c = (lane >> 4) * 8;

#pragma unroll
    for (int ks = 0; ks < 8; ks++) {
        unsigned af[4][4], bf[4][2];
#pragma unroll
        for (int mt = 0; mt < 4; mt++)
            ldsm4(af[mt][0], af[mt][1], af[mt][2], af[mt][3],
                  qb + (uint32_t)((wm0 + mt * 16 + a_r) * 136 + ks * 16 + a_c) * 2);
#pragma unroll
        for (int nq = 0; nq < 2; nq++)
            ldsm4t(bf[2 * nq][0], bf[2 * nq][1], bf[2 * nq + 1][0], bf[2 * nq + 1][1],
                   cb2 + (uint32_t)((ks * 16 + a_r) * 136 + wn0 + nq * 16 + a_c) * 2);
#pragma unroll
        for (int mt = 0; mt < 4; mt++)
#pragma unroll
            for (int nt = 0; nt < 4; nt++)
                mma_f16(acc[mt][nt], af[mt], bf[nt]);
    }

#pragma unroll
    for (int mt = 0; mt < 4; mt++) {
        size_t r0 = (size_t)(b * NN + tile * 128 + wm0 + mt * 16 + g);
#pragma unroll
        for (int nt = 0; nt < 4; nt++) {
            int col = h * DD + wn0 + nt * 8 + 2 * tq;
            __half2 h0 = __floats2half2_rn(acc[mt][nt][0], acc[mt][nt][1]);
            __half2 h1 = __floats2half2_rn(acc[mt][nt][2], acc[mt][nt][3]);
            *(__half2*)(attnh + r0 * CC + col) = h0;
            *(__half2*)(attnh + (r0 + 8) * CC + col) = h1;
        }
    }
}

// ---------------- launch ----------------
extern "C" void kernel_launch(void* const* d_in, const int* in_sizes, int n_in,
                              void* d_out, int out_size) {
    const float* x       = (const float*)d_in[0];
    const float* norm1_w = (const float*)d_in[1];
    const float* norm1_b = (const float*)d_in[2];
    const float* qkv_w   = (const float*)d_in[3];
    const float* qkv_b   = (const float*)d_in[4];
    const float* lnk_w   = (const float*)d_in[5];
    const float* lnk_b   = (const float*)d_in[6];
    const float* lnv_w   = (const float*)d_in[7];
    const float* lnv_b   = (const float*)d_in[8];
    const float* proj_w  = (const float*)d_in[9];
    const float* proj_b  = (const float*)d_in[10];
    const float* norm2_w = (const float*)d_in[11];
    const float* norm2_b = (const float*)d_in[12];
    const float* mlp_w1  = (const float*)d_in[13];
    const float* mlp_b1  = (const float*)d_in[14];
    const float* mlp_w2  = (const float*)d_in[15];
    const float* mlp_b2  = (const float*)d_in[16];
    float* out = (float*)d_out;

    float  *x1, *ctxp;
    __half *xh, *qkvh, *attnh, *mlphh, *ctxh, *wh;
    cudaGetSymbolAddress((void**)&x1,    g_x1);
    cudaGetSymbolAddress((void**)&ctxp,  g_ctxp);
    cudaGetSymbolAddress((void**)&xh,    g_xh);
    cudaGetSymbolAddress((void**)&qkvh,  g_qkvh);
    cudaGetSymbolAddress((void**)&attnh, g_attnh);
    cudaGetSymbolAddress((void**)&mlphh, g_mlphh);
    cudaGetSymbolAddress((void**)&ctxh,  g_ctxh);
    cudaGetSymbolAddress((void**)&wh,    g_wh);

    cudaFuncSetAttribute(hgemm<1536, 512, 0, 1, EPI_QKV>,
                         cudaFuncAttributeMaxDynamicSharedMemorySize, HSM_BYTES);
    cudaFuncSetAttribute(hgemm<512, 512, 1, 0, EPI_RES>,
                         cudaFuncAttributeMaxDynamicSharedMemorySize, HSM_BYTES);
    cudaFuncSetAttribute(hgemm<2048, 512, 0, 1, EPI_GELU>,
                         cudaFuncAttributeMaxDynamicSharedMemorySize, HSM_BYTES);
    cudaFuncSetAttribute(hgemm<512, 2048, 1, 0, EPI_RES>,
                         cudaFuncAttributeMaxDynamicSharedMemorySize, HSM_BYTES);
    cudaFuncSetAttribute(attn_mma,
                         cudaFuncAttributeMaxDynamicSharedMemorySize, ASM_BYTES);

    // 0. all weights -> fp16 (one launch)
    f2h_all<<<3072, 256>>>(qkv_w, proj_w, mlp_w1, mlp_w2, wh);

    // 1. LN1 -> fp16
    ln_rows512<<<MTOK, 256>>>(x, xh, norm1_w, norm1_b);
    // 2. qkv = xn @ qkv_w + b, with fused k/v LayerNorm, fp16 out
    hgemm<1536, 512, 0, 1, EPI_QKV><<<dim3(6, 256), 256, HSM_BYTES>>>(
        xh, wh + WH_QKV, nullptr, qkvh, qkv_b, nullptr, lnk_w, lnk_b, lnv_w, lnv_b);
    // 3. context = k^T v (tensor-core split-K) ; reduce * SCALE -> fp16
    ctx_mma<<<dim3(16, CSPLIT), 256>>>(qkvh, ctxp);
    reduce_ctx<<<1024, 256>>>(ctxp, ctxh);
    // 4. attn = q @ ctx  -> fp16
    attn_mma<<<dim3(64, 16), 256, ASM_BYTES>>>(qkvh, ctxh, attnh);
    // 5. x1 = x + attn @ proj_w + b  (fp32)
    hgemm<512, 512, 1, 0, EPI_RES><<<dim3(2, 256), 256, HSM_BYTES>>>(
        attnh, wh + WH_PROJ, x1, nullptr, proj_b, x, nullptr, nullptr, nullptr, nullptr);
    // 6. LN2 -> fp16
    ln_rows512<<<MTOK, 256>>>(x1, xh, norm2_w, norm2_b);
    // 7. mlp hidden = gelu(h @ w1 + b1)  (fp16 only)
    hgemm<2048, 512, 0, 1, EPI_GELU><<<dim3(8, 256), 256, HSM_BYTES>>>(
        xh, wh + WH_MLP1, nullptr, mlphh, mlp_b1, nullptr, nullptr, nullptr, nullptr, nullptr);
    // 8. out = x1 + mlph @ w2 + b2  (fp32)
    hgemm<512, 2048, 1, 0, EPI_RES><<<dim3(2, 256), 256, HSM_BYTES>>>(
        mlphh, wh + WH_MLP2, out, nullptr, mlp_b2, x1, nullptr, nullptr, nullptr, nullptr);
}